// round 1
// baseline (speedup 1.0000x reference)
#include <cuda_runtime.h>
#include <math.h>

// Problem constants
#define T_DIM   4
#define H_DIM   256
#define W_DIM   256
#define C_DIM   256
#define PS      8
#define NH      8
#define HD      32
#define NTOK    64            // PS*PS
#define WIN_X   32            // W/PS
#define WIN_Y   32            // H/PS
#define NWIN    4096          // T * WIN_Y * WIN_X
#define NROWS   (NWIN * NTOK) // 262144

// Scratch (allocation-free rule: __device__ globals)
__device__ float g_q[(size_t)NWIN * NH * NTOK * HD]; // [n][h][p][d]
__device__ float g_k[(size_t)NWIN * NH * NTOK * HD];
__device__ float g_v[(size_t)NWIN * NH * NTOK * HD];
__device__ float g_o[(size_t)NROWS * C_DIM];          // [n][p][c]

// ---------------------------------------------------------------------------
// Kernel A: fused window-gather + modulator + X @ [wq | wkv] + bias (+scale q)
// Tile: BM=64 (one window), BN=64, BK=16; 256 threads, 4x4 microtile.
// grid = (768/64 = 12, NWIN)
// ---------------------------------------------------------------------------
__global__ __launch_bounds__(256) void qkv_kernel(
    const float* __restrict__ vid, const float* __restrict__ modu,
    const float* __restrict__ wq,  const float* __restrict__ bq,
    const float* __restrict__ wkv, const float* __restrict__ bkv)
{
    __shared__ float As[16][64];
    __shared__ float Bs[16][64];

    const int n   = blockIdx.y;
    const int c0  = blockIdx.x * 64;
    const int tid = threadIdx.x;

    // A-load mapping: thread -> (token row, k-quad)
    const int arow = tid >> 2;   // 0..63
    const int akq  = tid & 3;    // 0..3 (float4 within 16-wide k tile)
    const int t_idx = n >> 10;
    const int wh    = (n >> 5) & 31;
    const int ww    = n & 31;
    const int py = arow >> 3, px = arow & 7;
    const size_t pix = (((size_t)t_idx * H_DIM + wh * PS + py) * W_DIM + ww * PS + px) * C_DIM;

    // B-load mapping: thread -> (k row, col-quad)
    const int bkr = tid >> 4;    // 0..15
    const int bcq = tid & 15;    // 0..15
    const int bc  = c0 + bcq * 4;
    const float* wsrc;
    int wstride, ccol;
    if (bc < C_DIM) { wsrc = wq;  wstride = C_DIM;     ccol = bc; }
    else            { wsrc = wkv; wstride = 2 * C_DIM; ccol = bc - C_DIM; }

    const int ty = tid >> 4, tx = tid & 15;

    float acc[4][4];
#pragma unroll
    for (int i = 0; i < 4; i++)
#pragma unroll
        for (int j = 0; j < 4; j++) acc[i][j] = 0.f;

    for (int k0 = 0; k0 < C_DIM; k0 += 16) {
        // A tile: x = vid(window pixel) + modulator(token)
        float4 av = *(const float4*)(vid  + pix + k0 + akq * 4);
        float4 mv = *(const float4*)(modu + (size_t)arow * C_DIM + k0 + akq * 4);
        As[akq * 4 + 0][arow] = av.x + mv.x;
        As[akq * 4 + 1][arow] = av.y + mv.y;
        As[akq * 4 + 2][arow] = av.z + mv.z;
        As[akq * 4 + 3][arow] = av.w + mv.w;
        // B tile
        *(float4*)&Bs[bkr][bcq * 4] =
            *(const float4*)(wsrc + (size_t)(k0 + bkr) * wstride + ccol);
        __syncthreads();

#pragma unroll
        for (int kk = 0; kk < 16; kk++) {
            float4 a4 = *(const float4*)&As[kk][ty * 4];
            float4 b4 = *(const float4*)&Bs[kk][tx * 4];
            float a[4] = {a4.x, a4.y, a4.z, a4.w};
            float b[4] = {b4.x, b4.y, b4.z, b4.w};
#pragma unroll
            for (int i = 0; i < 4; i++)
#pragma unroll
                for (int j = 0; j < 4; j++)
                    acc[i][j] = fmaf(a[i], b[j], acc[i][j]);
        }
        __syncthreads();
    }

    // Epilogue: bias, q-scale, scatter to [n][h][p][d] layout.
    const float sc = 0.1767766952966369f; // 1/sqrt(32)
    const int cc0 = c0 + tx * 4;          // 4 cols, all within one head (4 | 32)
#pragma unroll
    for (int i = 0; i < 4; i++) {
        const int p = ty * 4 + i;
        float4 v4;
        float* dst;
        int col0;
        if (cc0 < 256) {
            v4.x = (acc[i][0] + bq[cc0 + 0]) * sc;
            v4.y = (acc[i][1] + bq[cc0 + 1]) * sc;
            v4.z = (acc[i][2] + bq[cc0 + 2]) * sc;
            v4.w = (acc[i][3] + bq[cc0 + 3]) * sc;
            dst = g_q; col0 = cc0;
        } else {
            v4.x = acc[i][0] + bkv[cc0 - 256 + 0];
            v4.y = acc[i][1] + bkv[cc0 - 256 + 1];
            v4.z = acc[i][2] + bkv[cc0 - 256 + 2];
            v4.w = acc[i][3] + bkv[cc0 - 256 + 3];
            if (cc0 < 512) { dst = g_k; col0 = cc0 - 256; }
            else           { dst = g_v; col0 = cc0 - 512; }
        }
        const int hh = col0 >> 5, d0 = col0 & 31;
        *(float4*)(dst + (((size_t)n * NH + hh) * NTOK + p) * HD + d0) = v4;
    }
}

// ---------------------------------------------------------------------------
// Kernel B: attention per (window, head). 64 threads = 64 query rows.
// grid = NWIN*NH blocks.
// ---------------------------------------------------------------------------
__global__ __launch_bounds__(64) void attn_kernel(const float* __restrict__ rpt)
{
    __shared__ float ks[NTOK * HD];
    __shared__ float vs[NTOK * HD];
    __shared__ float bs[225];            // (2*PS-1)^2 bias entries for this head

    const int b = blockIdx.x;            // n*NH + h
    const int h = b & 7;
    const int n = b >> 3;
    const int tid = threadIdx.x;         // token p (query row)
    const size_t base = (size_t)b * (NTOK * HD);

    const float4* kg = (const float4*)(g_k + base);
    const float4* vg = (const float4*)(g_v + base);
    float4* ks4 = (float4*)ks;
    float4* vs4 = (float4*)vs;
#pragma unroll
    for (int i = tid; i < NTOK * HD / 4; i += 64) { ks4[i] = kg[i]; vs4[i] = vg[i]; }
    for (int i = tid; i < 225; i += 64) bs[i] = rpt[(size_t)i * NH + h];
    __syncthreads();

    // Query row in registers (already scaled in kernel A)
    float4 q[8];
    const float4* qg = (const float4*)(g_q + base + (size_t)tid * HD);
#pragma unroll
    for (int i = 0; i < 8; i++) q[i] = qg[i];

    const int qy = tid >> 3, qx = tid & 7;

    float s[64];
    float mx = -1e30f;
#pragma unroll 4
    for (int j = 0; j < 64; j++) {
        float acc = 0.f;
        const float4* kr = (const float4*)(ks + j * HD);
#pragma unroll
        for (int d = 0; d < 8; d++) {
            float4 kv = kr[d];
            acc = fmaf(q[d].x, kv.x, acc);
            acc = fmaf(q[d].y, kv.y, acc);
            acc = fmaf(q[d].z, kv.z, acc);
            acc = fmaf(q[d].w, kv.w, acc);
        }
        const int ky = j >> 3, kx = j & 7;
        acc += bs[(qy - ky + 7) * 15 + (qx - kx + 7)];
        s[j] = acc;
        mx = fmaxf(mx, acc);
    }

    float sum = 0.f;
#pragma unroll 4
    for (int j = 0; j < 64; j++) {
        float e = __expf(s[j] - mx);
        s[j] = e;
        sum += e;
    }
    const float inv = 1.0f / sum;

    float4 o[8];
#pragma unroll
    for (int d = 0; d < 8; d++) { o[d].x = o[d].y = o[d].z = o[d].w = 0.f; }
#pragma unroll 2
    for (int j = 0; j < 64; j++) {
        const float pj = s[j] * inv;
        const float4* vr = (const float4*)(vs + j * HD);
#pragma unroll
        for (int d = 0; d < 8; d++) {
            float4 vv = vr[d];
            o[d].x = fmaf(pj, vv.x, o[d].x);
            o[d].y = fmaf(pj, vv.y, o[d].y);
            o[d].z = fmaf(pj, vv.z, o[d].z);
            o[d].w = fmaf(pj, vv.w, o[d].w);
        }
    }

    float* og = g_o + ((size_t)n * NTOK + tid) * C_DIM + h * HD;
#pragma unroll
    for (int d = 0; d < 8; d++) ((float4*)og)[d] = o[d];
}

// ---------------------------------------------------------------------------
// Kernel C: proj GEMM (g_o @ proj_w + proj_b) + inverse window scatter to d_out
// grid = (256/64 = 4, NWIN)
// ---------------------------------------------------------------------------
__global__ __launch_bounds__(256) void proj_kernel(
    const float* __restrict__ pw, const float* __restrict__ pb,
    float* __restrict__ out)
{
    __shared__ float As[16][64];
    __shared__ float Bs[16][64];

    const int n   = blockIdx.y;
    const int c0  = blockIdx.x * 64;
    const int tid = threadIdx.x;

    const int arow = tid >> 2;
    const int akq  = tid & 3;
    const int bkr = tid >> 4;
    const int bcq = tid & 15;
    const int ty = tid >> 4, tx = tid & 15;

    float acc[4][4];
#pragma unroll
    for (int i = 0; i < 4; i++)
#pragma unroll
        for (int j = 0; j < 4; j++) acc[i][j] = 0.f;

    const float* arow_ptr = g_o + ((size_t)n * NTOK + arow) * C_DIM;

    for (int k0 = 0; k0 < C_DIM; k0 += 16) {
        float4 av = *(const float4*)(arow_ptr + k0 + akq * 4);
        As[akq * 4 + 0][arow] = av.x;
        As[akq * 4 + 1][arow] = av.y;
        As[akq * 4 + 2][arow] = av.z;
        As[akq * 4 + 3][arow] = av.w;
        *(float4*)&Bs[bkr][bcq * 4] =
            *(const float4*)(pw + (size_t)(k0 + bkr) * C_DIM + c0 + bcq * 4);
        __syncthreads();

#pragma unroll
        for (int kk = 0; kk < 16; kk++) {
            float4 a4 = *(const float4*)&As[kk][ty * 4];
            float4 b4 = *(const float4*)&Bs[kk][tx * 4];
            float a[4] = {a4.x, a4.y, a4.z, a4.w};
            float b[4] = {b4.x, b4.y, b4.z, b4.w};
#pragma unroll
            for (int i = 0; i < 4; i++)
#pragma unroll
                for (int j = 0; j < 4; j++)
                    acc[i][j] = fmaf(a[i], b[j], acc[i][j]);
        }
        __syncthreads();
    }

    // Epilogue: + proj_b, scatter back to (t, h, w, c)
    const int t_idx = n >> 10;
    const int wh    = (n >> 5) & 31;
    const int ww    = n & 31;
    const int cc0   = c0 + tx * 4;
    const float4 pb4 = *(const float4*)(pb + cc0);
#pragma unroll
    for (int i = 0; i < 4; i++) {
        const int p  = ty * 4 + i;
        const int py = p >> 3, px = p & 7;
        const size_t pix =
            (((size_t)t_idx * H_DIM + wh * PS + py) * W_DIM + ww * PS + px) * C_DIM;
        float4 v4;
        v4.x = acc[i][0] + pb4.x;
        v4.y = acc[i][1] + pb4.y;
        v4.z = acc[i][2] + pb4.z;
        v4.w = acc[i][3] + pb4.w;
        *(float4*)(out + pix + cc0) = v4;
    }
}

// ---------------------------------------------------------------------------
extern "C" void kernel_launch(void* const* d_in, const int* in_sizes, int n_in,
                              void* d_out, int out_size)
{
    const float* vid  = (const float*)d_in[0];
    const float* modu = (const float*)d_in[1];
    const float* wq   = (const float*)d_in[2];
    const float* bq   = (const float*)d_in[3];
    const float* wkv  = (const float*)d_in[4];
    const float* bkv  = (const float*)d_in[5];
    const float* pw   = (const float*)d_in[6];
    const float* pb   = (const float*)d_in[7];
    const float* rpt  = (const float*)d_in[8];
    float* out = (float*)d_out;

    qkv_kernel<<<dim3(12, NWIN), 256>>>(vid, modu, wq, bq, wkv, bkv);
    attn_kernel<<<NWIN * NH, 64>>>(rpt);
    proj_kernel<<<dim3(4, NWIN), 256>>>(pw, pb, out);
}

// round 2
// speedup vs baseline: 1.7523x; 1.7523x over previous
#include <cuda_runtime.h>
#include <math.h>
#include <stdint.h>

// Problem constants
#define T_DIM   4
#define H_DIM   256
#define W_DIM   256
#define C_DIM   256
#define PS      8
#define NH      8
#define HD      32
#define NTOK    64            // PS*PS
#define NWIN    4096          // T * 32 * 32
#define NROWS   (NWIN * NTOK) // 262144

// Scratch (allocation-free rule: __device__ globals)
__device__ float g_q[(size_t)NWIN * NH * NTOK * HD]; // [n][h][p][d]
__device__ float g_k[(size_t)NWIN * NH * NTOK * HD];
__device__ float g_v[(size_t)NWIN * NH * NTOK * HD];
__device__ float g_o[(size_t)NROWS * C_DIM];          // [n][p][c]

// ---------------------------------------------------------------------------
// TF32 helpers
// ---------------------------------------------------------------------------
__device__ __forceinline__ uint32_t f2tf(float x) {
    uint32_t r;
    asm("cvt.rna.tf32.f32 %0, %1;" : "=r"(r) : "f"(x));
    return r;
}

__device__ __forceinline__ void mma8(float* c, const uint32_t* a, const uint32_t* b) {
    asm volatile(
        "mma.sync.aligned.m16n8k8.row.col.f32.tf32.tf32.f32 "
        "{%0,%1,%2,%3}, {%4,%5,%6,%7}, {%8,%9}, {%0,%1,%2,%3};"
        : "+f"(c[0]), "+f"(c[1]), "+f"(c[2]), "+f"(c[3])
        : "r"(a[0]), "r"(a[1]), "r"(a[2]), "r"(a[3]), "r"(b[0]), "r"(b[1]));
}

#define KPAD 20   // k-stride padding: (20*g + t) mod 32 covers all banks

// ---------------------------------------------------------------------------
// Kernel A (TF32 MMA): window-gather + modulator + X @ [wq | wkv] + bias.
// BM=64 (one window), BN=128, BK=16, 256 thr = 8 warps (2m x 4n), warp 32x32.
// grid = (768/128 = 6, NWIN)
// ---------------------------------------------------------------------------
__global__ __launch_bounds__(256) void qkv_tc(
    const float* __restrict__ vid, const float* __restrict__ modu,
    const float* __restrict__ wq,  const float* __restrict__ bq,
    const float* __restrict__ wkv, const float* __restrict__ bkv)
{
    __shared__ uint32_t As[2][64][KPAD];
    __shared__ uint32_t Bs[2][128][KPAD];

    const int tid  = threadIdx.x;
    const int lane = tid & 31;
    const int warp = tid >> 5;
    const int wm   = warp >> 2;       // 0..1
    const int wn   = warp & 3;        // 0..3
    const int n    = blockIdx.y;
    const int n0   = blockIdx.x * 128;

    // ---- A gmem mapping: one float4 per thread per tile ----
    const int arow = tid >> 2;        // 0..63 (token)
    const int akq  = tid & 3;         // float4 index within 16-wide k
    const int t_idx = n >> 10;
    const int wh    = (n >> 5) & 31;
    const int ww    = n & 31;
    const int py = arow >> 3, px = arow & 7;
    const float* aptr = vid +
        (((size_t)t_idx * H_DIM + wh * PS + py) * W_DIM + ww * PS + px) * C_DIM;
    const float* mptr = modu + (size_t)arow * C_DIM;

    // ---- B gmem mapping: two float4 (8 cols) per thread per tile ----
    const int bk  = tid >> 4;         // 0..15 (k row)
    const int bnq = tid & 15;         // 8-col group
    const int bc  = n0 + bnq * 8;     // block col base (segment-uniform per block)
    const float* wsrc;
    int wstride, ccol;
    if (bc < C_DIM) { wsrc = wq;  wstride = C_DIM;     ccol = bc; }
    else            { wsrc = wkv; wstride = 2 * C_DIM; ccol = bc - C_DIM; }

    float acc[2][4][4];
#pragma unroll
    for (int i = 0; i < 2; i++)
#pragma unroll
        for (int j = 0; j < 4; j++)
#pragma unroll
            for (int e = 0; e < 4; e++) acc[i][j][e] = 0.f;

    // preload tile 0
    float4 av = *(const float4*)(aptr + akq * 4);
    float4 mv = *(const float4*)(mptr + akq * 4);
    float4 bv0 = *(const float4*)(wsrc + (size_t)bk * wstride + ccol);
    float4 bv1 = *(const float4*)(wsrc + (size_t)bk * wstride + ccol + 4);
    {
        uint4 a4;
        a4.x = f2tf(av.x + mv.x); a4.y = f2tf(av.y + mv.y);
        a4.z = f2tf(av.z + mv.z); a4.w = f2tf(av.w + mv.w);
        *(uint4*)&As[0][arow][akq * 4] = a4;
        float bvals[8] = {bv0.x, bv0.y, bv0.z, bv0.w, bv1.x, bv1.y, bv1.z, bv1.w};
#pragma unroll
        for (int j = 0; j < 8; j++) {
            int jj = (j + tid) & 7;   // rotate to break bank conflicts
            Bs[0][bnq * 8 + jj][bk] = f2tf(bvals[jj]);
        }
    }
    __syncthreads();

    int buf = 0;
#pragma unroll 1
    for (int it = 0; it < 16; ++it) {
        if (it < 15) {
            const int k0 = (it + 1) * 16;
            av  = *(const float4*)(aptr + k0 + akq * 4);
            mv  = *(const float4*)(mptr + k0 + akq * 4);
            bv0 = *(const float4*)(wsrc + (size_t)(k0 + bk) * wstride + ccol);
            bv1 = *(const float4*)(wsrc + (size_t)(k0 + bk) * wstride + ccol + 4);
        }

#pragma unroll
        for (int ks = 0; ks < 2; ks++) {
            const int kk = ks * 8;
            const int c  = kk + (lane & 3);
            uint32_t afr[2][4];
#pragma unroll
            for (int mf = 0; mf < 2; mf++) {
                const int r = wm * 32 + mf * 16 + (lane >> 2);
                afr[mf][0] = As[buf][r][c];
                afr[mf][1] = As[buf][r + 8][c];
                afr[mf][2] = As[buf][r][c + 4];
                afr[mf][3] = As[buf][r + 8][c + 4];
            }
            uint32_t bfr[4][2];
#pragma unroll
            for (int nf = 0; nf < 4; nf++) {
                const int nn = wn * 32 + nf * 8 + (lane >> 2);
                bfr[nf][0] = Bs[buf][nn][c];
                bfr[nf][1] = Bs[buf][nn][c + 4];
            }
#pragma unroll
            for (int mf = 0; mf < 2; mf++)
#pragma unroll
                for (int nf = 0; nf < 4; nf++)
                    mma8(acc[mf][nf], afr[mf], bfr[nf]);
        }

        if (it < 15) {
            uint4 a4;
            a4.x = f2tf(av.x + mv.x); a4.y = f2tf(av.y + mv.y);
            a4.z = f2tf(av.z + mv.z); a4.w = f2tf(av.w + mv.w);
            *(uint4*)&As[buf ^ 1][arow][akq * 4] = a4;
            float bvals[8] = {bv0.x, bv0.y, bv0.z, bv0.w, bv1.x, bv1.y, bv1.z, bv1.w};
#pragma unroll
            for (int j = 0; j < 8; j++) {
                int jj = (j + tid) & 7;
                Bs[buf ^ 1][bnq * 8 + jj][bk] = f2tf(bvals[jj]);
            }
        }
        __syncthreads();
        buf ^= 1;
    }

    // ---- Epilogue: bias (+ q scale), scatter to [n][h][p][d] ----
    const float sc = 0.1767766952966369f; // 1/sqrt(32)
#pragma unroll
    for (int mf = 0; mf < 2; mf++) {
#pragma unroll
        for (int nf = 0; nf < 4; nf++) {
            const int col = n0 + wn * 32 + nf * 8 + (lane & 3) * 2;
            const int row = wm * 32 + mf * 16 + (lane >> 2);
            const float* c4 = acc[mf][nf];
            float2 lo, hi;   // rows (row, row+8)
            float* dst;
            int cc;
            if (col < 256) {
                lo.x = (c4[0] + bq[col]) * sc;     lo.y = (c4[1] + bq[col + 1]) * sc;
                hi.x = (c4[2] + bq[col]) * sc;     hi.y = (c4[3] + bq[col + 1]) * sc;
                dst = g_q; cc = col;
            } else {
                const float b0 = bkv[col - 256], b1 = bkv[col - 255];
                lo.x = c4[0] + b0;  lo.y = c4[1] + b1;
                hi.x = c4[2] + b0;  hi.y = c4[3] + b1;
                if (col < 512) { dst = g_k; cc = col - 256; }
                else           { dst = g_v; cc = col - 512; }
            }
            const int hh = cc >> 5, d0 = cc & 31;
            float* p0 = dst + (((size_t)n * NH + hh) * NTOK + row) * HD + d0;
            *(float2*)p0 = lo;
            *(float2*)(p0 + 8 * HD) = hi;
        }
    }
}

// ---------------------------------------------------------------------------
// Kernel B: attention per (window, head). 64 threads = 64 query rows.
// ---------------------------------------------------------------------------
__global__ __launch_bounds__(64) void attn_kernel(const float* __restrict__ rpt)
{
    __shared__ float ks[NTOK * HD];
    __shared__ float vs[NTOK * HD];
    __shared__ float bs[225];

    const int b = blockIdx.x;            // n*NH + h
    const int h = b & 7;
    const int n = b >> 3;
    const int tid = threadIdx.x;
    const size_t base = (size_t)b * (NTOK * HD);

    const float4* kg = (const float4*)(g_k + base);
    const float4* vg = (const float4*)(g_v + base);
    float4* ks4 = (float4*)ks;
    float4* vs4 = (float4*)vs;
#pragma unroll
    for (int i = tid; i < NTOK * HD / 4; i += 64) { ks4[i] = kg[i]; vs4[i] = vg[i]; }
    for (int i = tid; i < 225; i += 64) bs[i] = rpt[(size_t)i * NH + h];
    __syncthreads();

    float4 q[8];
    const float4* qg = (const float4*)(g_q + base + (size_t)tid * HD);
#pragma unroll
    for (int i = 0; i < 8; i++) q[i] = qg[i];

    const int qy = tid >> 3, qx = tid & 7;

    float s[64];
    float mx = -1e30f;
#pragma unroll 4
    for (int j = 0; j < 64; j++) {
        float acc = 0.f;
        const float4* kr = (const float4*)(ks + j * HD);
#pragma unroll
        for (int d = 0; d < 8; d++) {
            float4 kv = kr[d];
            acc = fmaf(q[d].x, kv.x, acc);
            acc = fmaf(q[d].y, kv.y, acc);
            acc = fmaf(q[d].z, kv.z, acc);
            acc = fmaf(q[d].w, kv.w, acc);
        }
        const int ky = j >> 3, kx = j & 7;
        acc += bs[(qy - ky + 7) * 15 + (qx - kx + 7)];
        s[j] = acc;
        mx = fmaxf(mx, acc);
    }

    float sum = 0.f;
#pragma unroll 4
    for (int j = 0; j < 64; j++) {
        float e = __expf(s[j] - mx);
        s[j] = e;
        sum += e;
    }
    const float inv = 1.0f / sum;

    float4 o[8];
#pragma unroll
    for (int d = 0; d < 8; d++) { o[d].x = o[d].y = o[d].z = o[d].w = 0.f; }
#pragma unroll 2
    for (int j = 0; j < 64; j++) {
        const float pj = s[j] * inv;
        const float4* vr = (const float4*)(vs + j * HD);
#pragma unroll
        for (int d = 0; d < 8; d++) {
            float4 vv = vr[d];
            o[d].x = fmaf(pj, vv.x, o[d].x);
            o[d].y = fmaf(pj, vv.y, o[d].y);
            o[d].z = fmaf(pj, vv.z, o[d].z);
            o[d].w = fmaf(pj, vv.w, o[d].w);
        }
    }

    float* og = g_o + ((size_t)n * NTOK + tid) * C_DIM + h * HD;
#pragma unroll
    for (int d = 0; d < 8; d++) ((float4*)og)[d] = o[d];
}

// ---------------------------------------------------------------------------
// Kernel C (TF32 MMA): proj GEMM (g_o @ proj_w + proj_b) + window scatter.
// BM=64, BN=128, grid = (2, NWIN)
// ---------------------------------------------------------------------------
__global__ __launch_bounds__(256) void proj_tc(
    const float* __restrict__ pw, const float* __restrict__ pb,
    float* __restrict__ out)
{
    __shared__ uint32_t As[2][64][KPAD];
    __shared__ uint32_t Bs[2][128][KPAD];

    const int tid  = threadIdx.x;
    const int lane = tid & 31;
    const int warp = tid >> 5;
    const int wm   = warp >> 2;
    const int wn   = warp & 3;
    const int n    = blockIdx.y;
    const int n0   = blockIdx.x * 128;

    const int arow = tid >> 2;
    const int akq  = tid & 3;
    const float* aptr = g_o + ((size_t)n * NTOK + arow) * C_DIM;

    const int bk  = tid >> 4;
    const int bnq = tid & 15;
    const int ccol = n0 + bnq * 8;

    float acc[2][4][4];
#pragma unroll
    for (int i = 0; i < 2; i++)
#pragma unroll
        for (int j = 0; j < 4; j++)
#pragma unroll
            for (int e = 0; e < 4; e++) acc[i][j][e] = 0.f;

    float4 av  = *(const float4*)(aptr + akq * 4);
    float4 bv0 = *(const float4*)(pw + (size_t)bk * C_DIM + ccol);
    float4 bv1 = *(const float4*)(pw + (size_t)bk * C_DIM + ccol + 4);
    {
        uint4 a4;
        a4.x = f2tf(av.x); a4.y = f2tf(av.y); a4.z = f2tf(av.z); a4.w = f2tf(av.w);
        *(uint4*)&As[0][arow][akq * 4] = a4;
        float bvals[8] = {bv0.x, bv0.y, bv0.z, bv0.w, bv1.x, bv1.y, bv1.z, bv1.w};
#pragma unroll
        for (int j = 0; j < 8; j++) {
            int jj = (j + tid) & 7;
            Bs[0][bnq * 8 + jj][bk] = f2tf(bvals[jj]);
        }
    }
    __syncthreads();

    int buf = 0;
#pragma unroll 1
    for (int it = 0; it < 16; ++it) {
        if (it < 15) {
            const int k0 = (it + 1) * 16;
            av  = *(const float4*)(aptr + k0 + akq * 4);
            bv0 = *(const float4*)(pw + (size_t)(k0 + bk) * C_DIM + ccol);
            bv1 = *(const float4*)(pw + (size_t)(k0 + bk) * C_DIM + ccol + 4);
        }

#pragma unroll
        for (int ks = 0; ks < 2; ks++) {
            const int kk = ks * 8;
            const int c  = kk + (lane & 3);
            uint32_t afr[2][4];
#pragma unroll
            for (int mf = 0; mf < 2; mf++) {
                const int r = wm * 32 + mf * 16 + (lane >> 2);
                afr[mf][0] = As[buf][r][c];
                afr[mf][1] = As[buf][r + 8][c];
                afr[mf][2] = As[buf][r][c + 4];
                afr[mf][3] = As[buf][r + 8][c + 4];
            }
            uint32_t bfr[4][2];
#pragma unroll
            for (int nf = 0; nf < 4; nf++) {
                const int nn = wn * 32 + nf * 8 + (lane >> 2);
                bfr[nf][0] = Bs[buf][nn][c];
                bfr[nf][1] = Bs[buf][nn][c + 4];
            }
#pragma unroll
            for (int mf = 0; mf < 2; mf++)
#pragma unroll
                for (int nf = 0; nf < 4; nf++)
                    mma8(acc[mf][nf], afr[mf], bfr[nf]);
        }

        if (it < 15) {
            uint4 a4;
            a4.x = f2tf(av.x); a4.y = f2tf(av.y); a4.z = f2tf(av.z); a4.w = f2tf(av.w);
            *(uint4*)&As[buf ^ 1][arow][akq * 4] = a4;
            float bvals[8] = {bv0.x, bv0.y, bv0.z, bv0.w, bv1.x, bv1.y, bv1.z, bv1.w};
#pragma unroll
            for (int j = 0; j < 8; j++) {
                int jj = (j + tid) & 7;
                Bs[buf ^ 1][bnq * 8 + jj][bk] = f2tf(bvals[jj]);
            }
        }
        __syncthreads();
        buf ^= 1;
    }

    // ---- Epilogue: + proj_b, inverse window scatter to (t,h,w,c) ----
    const int t_idx = n >> 10;
    const int wh    = (n >> 5) & 31;
    const int ww    = n & 31;
#pragma unroll
    for (int mf = 0; mf < 2; mf++) {
#pragma unroll
        for (int nf = 0; nf < 4; nf++) {
            const int col = n0 + wn * 32 + nf * 8 + (lane & 3) * 2;
            const int row = wm * 32 + mf * 16 + (lane >> 2);
            const float* c4 = acc[mf][nf];
            const float b0 = pb[col], b1 = pb[col + 1];
#pragma unroll
            for (int half = 0; half < 2; half++) {
                const int p  = row + half * 8;
                const int py = p >> 3, px = p & 7;
                const size_t pix =
                    (((size_t)t_idx * H_DIM + wh * PS + py) * W_DIM + ww * PS + px) * C_DIM;
                float2 v2;
                v2.x = c4[half * 2 + 0] + b0;
                v2.y = c4[half * 2 + 1] + b1;
                *(float2*)(out + pix + col) = v2;
            }
        }
    }
}

// ---------------------------------------------------------------------------
extern "C" void kernel_launch(void* const* d_in, const int* in_sizes, int n_in,
                              void* d_out, int out_size)
{
    const float* vid  = (const float*)d_in[0];
    const float* modu = (const float*)d_in[1];
    const float* wq   = (const float*)d_in[2];
    const float* bq   = (const float*)d_in[3];
    const float* wkv  = (const float*)d_in[4];
    const float* bkv  = (const float*)d_in[5];
    const float* pw   = (const float*)d_in[6];
    const float* pb   = (const float*)d_in[7];
    const float* rpt  = (const float*)d_in[8];
    float* out = (float*)d_out;

    qkv_tc<<<dim3(6, NWIN), 256>>>(vid, modu, wq, bq, wkv, bkv);
    attn_kernel<<<NWIN * NH, 64>>>(rpt);
    proj_tc<<<dim3(2, NWIN), 256>>>(pw, pb, out);
}

// round 3
// speedup vs baseline: 2.1246x; 1.2125x over previous
#include <cuda_runtime.h>
#include <math.h>
#include <stdint.h>

// Problem constants
#define T_DIM   4
#define H_DIM   256
#define W_DIM   256
#define C_DIM   256
#define PS      8
#define NH      8
#define HD      32
#define NTOK    64
#define NWIN    4096
#define NROWS   (NWIN * NTOK)

// Scratch (allocation-free rule: __device__ globals)
__device__ float g_q[(size_t)NWIN * NH * NTOK * HD]; // [n][h][p][d]
__device__ float g_k[(size_t)NWIN * NH * NTOK * HD];
__device__ float g_v[(size_t)NWIN * NH * NTOK * HD];
__device__ float g_o[(size_t)NROWS * C_DIM];         // [n][p][c]
__device__ uint32_t g_wb[256 * 768];                 // tf32 [k][n]: [wq*sc | wkv]
__device__ uint32_t g_pw[256 * 256];                 // tf32 [k][n]: proj_w
__device__ float    g_bias[768];                     // [bq*sc | bkv]

// ---------------------------------------------------------------------------
__device__ __forceinline__ uint32_t f2tf(float x) {
    uint32_t r;
    asm("cvt.rna.tf32.f32 %0, %1;" : "=r"(r) : "f"(x));
    return r;
}
__device__ __forceinline__ void mma8(float* c, const uint32_t* a, const uint32_t* b) {
    asm volatile(
        "mma.sync.aligned.m16n8k8.row.col.f32.tf32.tf32.f32 "
        "{%0,%1,%2,%3}, {%4,%5,%6,%7}, {%8,%9}, {%0,%1,%2,%3};"
        : "+f"(c[0]), "+f"(c[1]), "+f"(c[2]), "+f"(c[3])
        : "r"(a[0]), "r"(a[1]), "r"(a[2]), "r"(a[3]), "r"(b[0]), "r"(b[1]));
}
__device__ __forceinline__ void cp16(uint32_t s, const void* g) {
    asm volatile("cp.async.ca.shared.global [%0], [%1], 16;" :: "r"(s), "l"(g));
}
#define CP_COMMIT() asm volatile("cp.async.commit_group;")
#define CP_WAIT0()  asm volatile("cp.async.wait_group 0;")

#define APAD 20     // A smem k-stride (words): banks (20*(lane>>2)+(lane&3)) all distinct
#define BSTR 136    // B smem n-stride (words): banks (8*(lane&3)+(lane>>2)) all distinct

// ---------------------------------------------------------------------------
// Prep: tf32-convert weights (scale folded into wq), pack bias.
// grid 1024 x 256
// ---------------------------------------------------------------------------
__global__ __launch_bounds__(256) void prep_kernel(
    const float* __restrict__ wq,  const float* __restrict__ bq,
    const float* __restrict__ wkv, const float* __restrict__ bkv,
    const float* __restrict__ pw)
{
    const float sc = 0.1767766952966369f; // 1/sqrt(32)
    int idx = blockIdx.x * 256 + threadIdx.x;
    if (idx < 196608) {
        int k = idx / 768, c = idx % 768;
        float v = (c < 256) ? wq[k * 256 + c] * sc : wkv[k * 512 + (c - 256)];
        g_wb[idx] = f2tf(v);
    } else {
        int j = idx - 196608;
        g_pw[j] = f2tf(pw[j]);
    }
    if (idx < 768) g_bias[idx] = (idx < 256) ? bq[idx] * sc : bkv[idx - 256];
}

// ---------------------------------------------------------------------------
// Kernel A (TF32 MMA): window-gather + modulator + X @ [wq|wkv] (pre-tf32).
// BM=64 (one window), BN=128, BK=16, 256 thr = 8 warps (2m x 4n).
// grid = (6, NWIN)
// ---------------------------------------------------------------------------
__global__ __launch_bounds__(256) void qkv_tc(
    const float* __restrict__ vid, const float* __restrict__ modu)
{
    __shared__ uint32_t As[2][64][APAD];
    __shared__ uint32_t Bs[2][16][BSTR];

    const int tid  = threadIdx.x;
    const int lane = tid & 31;
    const int warp = tid >> 5;
    const int wm   = warp >> 2;
    const int wn   = warp & 3;
    const int n    = blockIdx.y;
    const int n0   = blockIdx.x * 128;

    // A gmem mapping
    const int arow = tid >> 2;
    const int akq  = tid & 3;
    const int t_idx = n >> 10;
    const int wh    = (n >> 5) & 31;
    const int ww    = n & 31;
    const int py = arow >> 3, px = arow & 7;
    const float* aptr = vid +
        (((size_t)t_idx * H_DIM + wh * PS + py) * W_DIM + ww * PS + px) * C_DIM;
    const float* mptr = modu + (size_t)arow * C_DIM;

    // B cp.async mapping: row = tid>>4 (0..15), 8 cols at (tid&15)*8
    const int brow = tid >> 4;
    const int bq8  = tid & 15;
    const uint32_t* gw = g_wb + (size_t)brow * 768 + n0 + bq8 * 8;
    const uint32_t bs_s = (uint32_t)__cvta_generic_to_shared(Bs);
    const uint32_t bdst = bs_s + (uint32_t)(brow * BSTR + bq8 * 8) * 4;
    const uint32_t bufstride = 16 * BSTR * 4;

    float acc[2][4][4];
#pragma unroll
    for (int i = 0; i < 2; i++)
#pragma unroll
        for (int j = 0; j < 4; j++)
#pragma unroll
            for (int e = 0; e < 4; e++) acc[i][j][e] = 0.f;

    // Prologue: tile 0
    cp16(bdst,      gw);
    cp16(bdst + 16, gw + 4);
    CP_COMMIT();
    {
        float4 av = *(const float4*)(aptr + akq * 4);
        float4 mv = *(const float4*)(mptr + akq * 4);
        uint4 a4;
        a4.x = f2tf(av.x + mv.x); a4.y = f2tf(av.y + mv.y);
        a4.z = f2tf(av.z + mv.z); a4.w = f2tf(av.w + mv.w);
        *(uint4*)&As[0][arow][akq * 4] = a4;
    }
    CP_WAIT0();
    __syncthreads();

    int buf = 0;
    float4 av, mv;
#pragma unroll 1
    for (int it = 0; it < 16; ++it) {
        if (it < 15) {
            const int k0 = (it + 1) * 16;
            const uint32_t d = bdst + (buf ^ 1) * bufstride;
            const uint32_t* g = gw + (size_t)k0 * 768;
            cp16(d,      g);
            cp16(d + 16, g + 4);
            CP_COMMIT();
            av = *(const float4*)(aptr + k0 + akq * 4);
            mv = *(const float4*)(mptr + k0 + akq * 4);
        }

#pragma unroll
        for (int ks = 0; ks < 2; ks++) {
            const int c = ks * 8 + (lane & 3);
            uint32_t afr[2][4];
#pragma unroll
            for (int mf = 0; mf < 2; mf++) {
                const int r = wm * 32 + mf * 16 + (lane >> 2);
                afr[mf][0] = As[buf][r][c];
                afr[mf][1] = As[buf][r + 8][c];
                afr[mf][2] = As[buf][r][c + 4];
                afr[mf][3] = As[buf][r + 8][c + 4];
            }
            uint32_t bfr[4][2];
#pragma unroll
            for (int nf = 0; nf < 4; nf++) {
                const int nn = wn * 32 + nf * 8 + (lane >> 2);
                bfr[nf][0] = Bs[buf][c][nn];
                bfr[nf][1] = Bs[buf][c + 4][nn];
            }
#pragma unroll
            for (int mf = 0; mf < 2; mf++)
#pragma unroll
                for (int nf = 0; nf < 4; nf++)
                    mma8(acc[mf][nf], afr[mf], bfr[nf]);
        }

        if (it < 15) {
            uint4 a4;
            a4.x = f2tf(av.x + mv.x); a4.y = f2tf(av.y + mv.y);
            a4.z = f2tf(av.z + mv.z); a4.w = f2tf(av.w + mv.w);
            *(uint4*)&As[buf ^ 1][arow][akq * 4] = a4;
            CP_WAIT0();
        }
        __syncthreads();
        buf ^= 1;
    }

    // Epilogue: + bias (scale pre-folded), scatter to [n][h][p][d]
#pragma unroll
    for (int mf = 0; mf < 2; mf++) {
#pragma unroll
        for (int nf = 0; nf < 4; nf++) {
            const int col = n0 + wn * 32 + nf * 8 + (lane & 3) * 2;
            const int row = wm * 32 + mf * 16 + (lane >> 2);
            const float* c4 = acc[mf][nf];
            const float b0 = g_bias[col], b1 = g_bias[col + 1];
            float2 lo, hi;
            lo.x = c4[0] + b0; lo.y = c4[1] + b1;
            hi.x = c4[2] + b0; hi.y = c4[3] + b1;
            float* dst;
            int cc;
            if (col < 256)      { dst = g_q; cc = col; }
            else if (col < 512) { dst = g_k; cc = col - 256; }
            else                { dst = g_v; cc = col - 512; }
            const int hh = cc >> 5, d0 = cc & 31;
            float* p0 = dst + (((size_t)n * NH + hh) * NTOK + row) * HD + d0;
            *(float2*)p0 = lo;
            *(float2*)(p0 + 8 * HD) = hi;
        }
    }
}

// ---------------------------------------------------------------------------
// Kernel B: attention per (window, head). 64 threads = 64 query rows.
// ---------------------------------------------------------------------------
__global__ __launch_bounds__(64) void attn_kernel(const float* __restrict__ rpt)
{
    __shared__ float ks[NTOK * HD];
    __shared__ float vs[NTOK * HD];
    __shared__ float bs[225];

    const int b = blockIdx.x;
    const int h = b & 7;
    const int n = b >> 3;
    const int tid = threadIdx.x;
    const size_t base = (size_t)b * (NTOK * HD);

    const float4* kg = (const float4*)(g_k + base);
    const float4* vg = (const float4*)(g_v + base);
    float4* ks4 = (float4*)ks;
    float4* vs4 = (float4*)vs;
#pragma unroll
    for (int i = tid; i < NTOK * HD / 4; i += 64) { ks4[i] = kg[i]; vs4[i] = vg[i]; }
    for (int i = tid; i < 225; i += 64) bs[i] = rpt[(size_t)i * NH + h];
    __syncthreads();

    float4 q[8];
    const float4* qg = (const float4*)(g_q + base + (size_t)tid * HD);
#pragma unroll
    for (int i = 0; i < 8; i++) q[i] = qg[i];

    const int qy = tid >> 3, qx = tid & 7;

    float s[64];
    float mx = -1e30f;
#pragma unroll 4
    for (int j = 0; j < 64; j++) {
        float acc = 0.f;
        const float4* kr = (const float4*)(ks + j * HD);
#pragma unroll
        for (int d = 0; d < 8; d++) {
            float4 kv = kr[d];
            acc = fmaf(q[d].x, kv.x, acc);
            acc = fmaf(q[d].y, kv.y, acc);
            acc = fmaf(q[d].z, kv.z, acc);
            acc = fmaf(q[d].w, kv.w, acc);
        }
        const int ky = j >> 3, kx = j & 7;
        acc += bs[(qy - ky + 7) * 15 + (qx - kx + 7)];
        s[j] = acc;
        mx = fmaxf(mx, acc);
    }

    float sum = 0.f;
#pragma unroll 4
    for (int j = 0; j < 64; j++) {
        float e = __expf(s[j] - mx);
        s[j] = e;
        sum += e;
    }
    const float inv = 1.0f / sum;

    float4 o[8];
#pragma unroll
    for (int d = 0; d < 8; d++) { o[d].x = o[d].y = o[d].z = o[d].w = 0.f; }
#pragma unroll 2
    for (int j = 0; j < 64; j++) {
        const float pj = s[j] * inv;
        const float4* vr = (const float4*)(vs + j * HD);
#pragma unroll
        for (int d = 0; d < 8; d++) {
            float4 vv = vr[d];
            o[d].x = fmaf(pj, vv.x, o[d].x);
            o[d].y = fmaf(pj, vv.y, o[d].y);
            o[d].z = fmaf(pj, vv.z, o[d].z);
            o[d].w = fmaf(pj, vv.w, o[d].w);
        }
    }

    float* og = g_o + ((size_t)n * NTOK + tid) * C_DIM + h * HD;
#pragma unroll
    for (int d = 0; d < 8; d++) ((float4*)og)[d] = o[d];
}

// ---------------------------------------------------------------------------
// Kernel C (TF32 MMA): proj GEMM (g_o @ proj_w + proj_b) + window scatter.
// BM=64, BN=128, grid = (2, NWIN)
// ---------------------------------------------------------------------------
__global__ __launch_bounds__(256) void proj_tc(
    const float* __restrict__ pb, float* __restrict__ out)
{
    __shared__ uint32_t As[2][64][APAD];
    __shared__ uint32_t Bs[2][16][BSTR];

    const int tid  = threadIdx.x;
    const int lane = tid & 31;
    const int warp = tid >> 5;
    const int wm   = warp >> 2;
    const int wn   = warp & 3;
    const int n    = blockIdx.y;
    const int n0   = blockIdx.x * 128;

    const int arow = tid >> 2;
    const int akq  = tid & 3;
    const float* aptr = g_o + ((size_t)n * NTOK + arow) * C_DIM;

    const int brow = tid >> 4;
    const int bq8  = tid & 15;
    const uint32_t* gw = g_pw + (size_t)brow * 256 + n0 + bq8 * 8;
    const uint32_t bs_s = (uint32_t)__cvta_generic_to_shared(Bs);
    const uint32_t bdst = bs_s + (uint32_t)(brow * BSTR + bq8 * 8) * 4;
    const uint32_t bufstride = 16 * BSTR * 4;

    float acc[2][4][4];
#pragma unroll
    for (int i = 0; i < 2; i++)
#pragma unroll
        for (int j = 0; j < 4; j++)
#pragma unroll
            for (int e = 0; e < 4; e++) acc[i][j][e] = 0.f;

    cp16(bdst,      gw);
    cp16(bdst + 16, gw + 4);
    CP_COMMIT();
    {
        float4 av = *(const float4*)(aptr + akq * 4);
        uint4 a4;
        a4.x = f2tf(av.x); a4.y = f2tf(av.y); a4.z = f2tf(av.z); a4.w = f2tf(av.w);
        *(uint4*)&As[0][arow][akq * 4] = a4;
    }
    CP_WAIT0();
    __syncthreads();

    int buf = 0;
    float4 av;
#pragma unroll 1
    for (int it = 0; it < 16; ++it) {
        if (it < 15) {
            const int k0 = (it + 1) * 16;
            const uint32_t d = bdst + (buf ^ 1) * bufstride;
            const uint32_t* g = gw + (size_t)k0 * 256;
            cp16(d,      g);
            cp16(d + 16, g + 4);
            CP_COMMIT();
            av = *(const float4*)(aptr + k0 + akq * 4);
        }

#pragma unroll
        for (int ks = 0; ks < 2; ks++) {
            const int c = ks * 8 + (lane & 3);
            uint32_t afr[2][4];
#pragma unroll
            for (int mf = 0; mf < 2; mf++) {
                const int r = wm * 32 + mf * 16 + (lane >> 2);
                afr[mf][0] = As[buf][r][c];
                afr[mf][1] = As[buf][r + 8][c];
                afr[mf][2] = As[buf][r][c + 4];
                afr[mf][3] = As[buf][r + 8][c + 4];
            }
            uint32_t bfr[4][2];
#pragma unroll
            for (int nf = 0; nf < 4; nf++) {
                const int nn = wn * 32 + nf * 8 + (lane >> 2);
                bfr[nf][0] = Bs[buf][c][nn];
                bfr[nf][1] = Bs[buf][c + 4][nn];
            }
#pragma unroll
            for (int mf = 0; mf < 2; mf++)
#pragma unroll
                for (int nf = 0; nf < 4; nf++)
                    mma8(acc[mf][nf], afr[mf], bfr[nf]);
        }

        if (it < 15) {
            uint4 a4;
            a4.x = f2tf(av.x); a4.y = f2tf(av.y); a4.z = f2tf(av.z); a4.w = f2tf(av.w);
            *(uint4*)&As[buf ^ 1][arow][akq * 4] = a4;
            CP_WAIT0();
        }
        __syncthreads();
        buf ^= 1;
    }

    // Epilogue: + proj_b, inverse window scatter to (t,h,w,c)
    const int t_idx = n >> 10;
    const int wh    = (n >> 5) & 31;
    const int ww    = n & 31;
#pragma unroll
    for (int mf = 0; mf < 2; mf++) {
#pragma unroll
        for (int nf = 0; nf < 4; nf++) {
            const int col = n0 + wn * 32 + nf * 8 + (lane & 3) * 2;
            const int row = wm * 32 + mf * 16 + (lane >> 2);
            const float* c4 = acc[mf][nf];
            const float b0 = pb[col], b1 = pb[col + 1];
#pragma unroll
            for (int half = 0; half < 2; half++) {
                const int p  = row + half * 8;
                const int py = p >> 3, px = p & 7;
                const size_t pix =
                    (((size_t)t_idx * H_DIM + wh * PS + py) * W_DIM + ww * PS + px) * C_DIM;
                float2 v2;
                v2.x = c4[half * 2 + 0] + b0;
                v2.y = c4[half * 2 + 1] + b1;
                *(float2*)(out + pix + col) = v2;
            }
        }
    }
}

// ---------------------------------------------------------------------------
extern "C" void kernel_launch(void* const* d_in, const int* in_sizes, int n_in,
                              void* d_out, int out_size)
{
    const float* vid  = (const float*)d_in[0];
    const float* modu = (const float*)d_in[1];
    const float* wq   = (const float*)d_in[2];
    const float* bq   = (const float*)d_in[3];
    const float* wkv  = (const float*)d_in[4];
    const float* bkv  = (const float*)d_in[5];
    const float* pw   = (const float*)d_in[6];
    const float* pb   = (const float*)d_in[7];
    const float* rpt  = (const float*)d_in[8];
    float* out = (float*)d_out;

    prep_kernel<<<1024, 256>>>(wq, bq, wkv, bkv, pw);
    qkv_tc<<<dim3(6, NWIN), 256>>>(vid, modu);
    attn_kernel<<<NWIN * NH, 64>>>(rpt);
    proj_tc<<<dim3(2, NWIN), 256>>>(pb, out);
}

// round 4
// speedup vs baseline: 2.1453x; 1.0097x over previous
#include <cuda_runtime.h>
#include <math.h>
#include <stdint.h>

// Problem constants
#define T_DIM   4
#define H_DIM   256
#define W_DIM   256
#define C_DIM   256
#define PS      8
#define NH      8
#define HD      32
#define NTOK    64
#define NWIN    4096
#define NROWS   (NWIN * NTOK)

// Scratch (allocation-free rule: __device__ globals)
__device__ float g_q[(size_t)NWIN * NH * NTOK * HD]; // [n][h][p][d]
__device__ float g_k[(size_t)NWIN * NH * NTOK * HD];
__device__ float g_v[(size_t)NWIN * NH * NTOK * HD];
__device__ float g_o[(size_t)NROWS * C_DIM];         // [n][p][c]
__device__ uint32_t g_wb[256 * 768];                 // tf32 [k][n]: [wq*sc | wkv]
__device__ uint32_t g_pw[256 * 256];                 // tf32 [k][n]: proj_w
__device__ float    g_bias[768];                     // [bq*sc | bkv]

// ---------------------------------------------------------------------------
__device__ __forceinline__ uint32_t f2tf(float x) {
    uint32_t r;
    asm("cvt.rna.tf32.f32 %0, %1;" : "=r"(r) : "f"(x));
    return r;
}
__device__ __forceinline__ void mma8(float* c, const uint32_t* a, const uint32_t* b) {
    asm volatile(
        "mma.sync.aligned.m16n8k8.row.col.f32.tf32.tf32.f32 "
        "{%0,%1,%2,%3}, {%4,%5,%6,%7}, {%8,%9}, {%0,%1,%2,%3};"
        : "+f"(c[0]), "+f"(c[1]), "+f"(c[2]), "+f"(c[3])
        : "r"(a[0]), "r"(a[1]), "r"(a[2]), "r"(a[3]), "r"(b[0]), "r"(b[1]));
}
__device__ __forceinline__ void cp16(uint32_t s, const void* g) {
    asm volatile("cp.async.ca.shared.global [%0], [%1], 16;" :: "r"(s), "l"(g));
}
#define CP_COMMIT() asm volatile("cp.async.commit_group;")
#define CP_WAIT0()  asm volatile("cp.async.wait_group 0;")

#define APAD 12     // A k-stride: banks (12g + t) mod 32 all distinct
#define BST  264    // B n-stride: 264 mod 32 = 8 -> banks (8t + g) all distinct

// ---------------------------------------------------------------------------
// Prep: tf32-convert weights (q-scale folded), pack bias.
// ---------------------------------------------------------------------------
__global__ __launch_bounds__(256) void prep_kernel(
    const float* __restrict__ wq,  const float* __restrict__ bq,
    const float* __restrict__ wkv, const float* __restrict__ bkv,
    const float* __restrict__ pw)
{
    const float sc = 0.1767766952966369f; // 1/sqrt(32)
    int idx = blockIdx.x * 256 + threadIdx.x;
    if (idx < 196608) {
        int k = idx / 768, c = idx % 768;
        float v = (c < 256) ? wq[k * 256 + c] * sc : wkv[k * 512 + (c - 256)];
        g_wb[idx] = f2tf(v);
    } else {
        int j = idx - 196608;
        g_pw[j] = f2tf(pw[j]);
    }
    if (idx < 768) g_bias[idx] = (idx < 256) ? bq[idx] * sc : bkv[idx - 256];
}

// ---------------------------------------------------------------------------
// Kernel A (TF32 MMA): gather + modulator + X @ [wq|wkv].
// BM=128 (2 windows), BN=256, BK=8 double-buffered. 8 warps (2m x 4n),
// warp tile 64x64. grid = (3, 2048). blockIdx.x selects q/k/v destination.
// ---------------------------------------------------------------------------
__global__ __launch_bounds__(256) void qkv_tc(
    const float* __restrict__ vid, const float* __restrict__ modu)
{
    __shared__ uint32_t As[2][128][APAD];
    __shared__ uint32_t Bs[2][8][BST];

    const int tid  = threadIdx.x;
    const int lane = tid & 31;
    const int warp = tid >> 5;
    const int wm   = warp >> 2;       // 0..1  -> rows wm*64
    const int wn   = warp & 3;        // 0..3  -> cols wn*64
    const int n2   = blockIdx.y * 2;  // first window of this block
    const int n0   = blockIdx.x * 256;

    // A gmem mapping: arow = tid>>1 (0..127), akq = tid&1 -> k = akq*4
    const int arow = tid >> 1;
    const int akq  = tid & 1;
    const int wgt  = n2 + (arow >> 6);   // window index
    const int p    = arow & 63;          // token
    const int t_idx = wgt >> 10, wh = (wgt >> 5) & 31, ww = wgt & 31;
    const int py = p >> 3, px = p & 7;
    const float* aptr = vid +
        (((size_t)t_idx * H_DIM + wh * PS + py) * W_DIM + ww * PS + px) * C_DIM + akq * 4;
    const float* mptr = modu + (size_t)p * C_DIM + akq * 4;

    // B cp.async mapping: 2 chunks of 16B per thread per tile
    const int r0 = tid >> 6,       c0c = tid & 63;
    const int r1 = (tid + 256) >> 6, c1c = tid & 63;   // r1 = r0 + 4
    const uint32_t bs_s = (uint32_t)__cvta_generic_to_shared(Bs);
    const uint32_t bd0 = bs_s + (uint32_t)(r0 * BST + c0c * 4) * 4;
    const uint32_t bd1 = bs_s + (uint32_t)(r1 * BST + c1c * 4) * 4;
    const uint32_t bufB = 8 * BST * 4;
    const uint32_t* gb0 = g_wb + (size_t)r0 * 768 + n0 + c0c * 4;
    const uint32_t* gb1 = g_wb + (size_t)r1 * 768 + n0 + c1c * 4;

    float acc[4][8][4];
#pragma unroll
    for (int i = 0; i < 4; i++)
#pragma unroll
        for (int j = 0; j < 8; j++)
#pragma unroll
            for (int e = 0; e < 4; e++) acc[i][j][e] = 0.f;

    // Prologue: tile 0
    cp16(bd0, gb0);
    cp16(bd1, gb1);
    CP_COMMIT();
    {
        float4 av = *(const float4*)aptr;
        float4 mv = *(const float4*)mptr;
        uint4 a4;
        a4.x = f2tf(av.x + mv.x); a4.y = f2tf(av.y + mv.y);
        a4.z = f2tf(av.z + mv.z); a4.w = f2tf(av.w + mv.w);
        *(uint4*)&As[0][arow][akq * 4] = a4;
    }
    CP_WAIT0();
    __syncthreads();

    int buf = 0;
    float4 av, mv;
#pragma unroll 1
    for (int it = 0; it < 32; ++it) {
        if (it < 31) {
            const int k0 = (it + 1) * 8;
            const uint32_t boff = (buf ^ 1) * bufB;
            cp16(bd0 + boff, gb0 + (size_t)k0 * 768);
            cp16(bd1 + boff, gb1 + (size_t)k0 * 768);
            CP_COMMIT();
            av = *(const float4*)(aptr + k0);
            mv = *(const float4*)(mptr + k0);
        }

        const int t = lane & 3, g = lane >> 2;
        uint32_t afr[4][4];
#pragma unroll
        for (int mf = 0; mf < 4; mf++) {
            const int r = wm * 64 + mf * 16 + g;
            afr[mf][0] = As[buf][r][t];
            afr[mf][1] = As[buf][r + 8][t];
            afr[mf][2] = As[buf][r][t + 4];
            afr[mf][3] = As[buf][r + 8][t + 4];
        }
        uint32_t bfr[8][2];
#pragma unroll
        for (int nf = 0; nf < 8; nf++) {
            const int nn = wn * 64 + nf * 8 + g;
            bfr[nf][0] = Bs[buf][t][nn];
            bfr[nf][1] = Bs[buf][t + 4][nn];
        }
#pragma unroll
        for (int mf = 0; mf < 4; mf++)
#pragma unroll
            for (int nf = 0; nf < 8; nf++)
                mma8(acc[mf][nf], afr[mf], bfr[nf]);

        if (it < 31) {
            uint4 a4;
            a4.x = f2tf(av.x + mv.x); a4.y = f2tf(av.y + mv.y);
            a4.z = f2tf(av.z + mv.z); a4.w = f2tf(av.w + mv.w);
            *(uint4*)&As[buf ^ 1][arow][akq * 4] = a4;
            CP_WAIT0();
        }
        __syncthreads();
        buf ^= 1;
    }

    // Epilogue: + bias, scatter to [n][h][p][d]; whole block -> one dst
    float* dst = (blockIdx.x == 0) ? g_q : (blockIdx.x == 1) ? g_k : g_v;
#pragma unroll
    for (int mf = 0; mf < 4; mf++) {
        const int row0 = wm * 64 + mf * 16 + (lane >> 2);
#pragma unroll
        for (int nf = 0; nf < 8; nf++) {
            const int cl = wn * 64 + nf * 8 + (lane & 3) * 2;   // 0..255
            const float b0 = g_bias[n0 + cl], b1 = g_bias[n0 + cl + 1];
            const int hh = cl >> 5, d0 = cl & 31;
            const float* c4 = acc[mf][nf];
#pragma unroll
            for (int half = 0; half < 2; half++) {
                const int row = row0 + half * 8;
                const int win = n2 + (row >> 6);
                const int pp  = row & 63;
                float2 v2;
                v2.x = c4[half * 2 + 0] + b0;
                v2.y = c4[half * 2 + 1] + b1;
                *(float2*)(dst + (((size_t)win * NH + hh) * NTOK + pp) * HD + d0) = v2;
            }
        }
    }
}

// ---------------------------------------------------------------------------
// Kernel B: attention per (window, head). 64 threads = 64 query rows.
// ---------------------------------------------------------------------------
__global__ __launch_bounds__(64) void attn_kernel(const float* __restrict__ rpt)
{
    __shared__ float ks[NTOK * HD];
    __shared__ float vs[NTOK * HD];
    __shared__ float bs[225];

    const int b = blockIdx.x;
    const int h = b & 7;
    const int n = b >> 3;
    const int tid = threadIdx.x;
    const size_t base = (size_t)b * (NTOK * HD);

    const float4* kg = (const float4*)(g_k + base);
    const float4* vg = (const float4*)(g_v + base);
    float4* ks4 = (float4*)ks;
    float4* vs4 = (float4*)vs;
#pragma unroll
    for (int i = tid; i < NTOK * HD / 4; i += 64) { ks4[i] = kg[i]; vs4[i] = vg[i]; }
    for (int i = tid; i < 225; i += 64) bs[i] = rpt[(size_t)i * NH + h];
    __syncthreads();

    float4 q[8];
    const float4* qg = (const float4*)(g_q + base + (size_t)tid * HD);
#pragma unroll
    for (int i = 0; i < 8; i++) q[i] = qg[i];

    const int qy = tid >> 3, qx = tid & 7;

    float s[64];
    float mx = -1e30f;
#pragma unroll 4
    for (int j = 0; j < 64; j++) {
        float acc = 0.f;
        const float4* kr = (const float4*)(ks + j * HD);
#pragma unroll
        for (int d = 0; d < 8; d++) {
            float4 kv = kr[d];
            acc = fmaf(q[d].x, kv.x, acc);
            acc = fmaf(q[d].y, kv.y, acc);
            acc = fmaf(q[d].z, kv.z, acc);
            acc = fmaf(q[d].w, kv.w, acc);
        }
        const int ky = j >> 3, kx = j & 7;
        acc += bs[(qy - ky + 7) * 15 + (qx - kx + 7)];
        s[j] = acc;
        mx = fmaxf(mx, acc);
    }

    float sum = 0.f;
#pragma unroll 4
    for (int j = 0; j < 64; j++) {
        float e = __expf(s[j] - mx);
        s[j] = e;
        sum += e;
    }
    const float inv = 1.0f / sum;

    float4 o[8];
#pragma unroll
    for (int d = 0; d < 8; d++) { o[d].x = o[d].y = o[d].z = o[d].w = 0.f; }
#pragma unroll 2
    for (int j = 0; j < 64; j++) {
        const float pj = s[j] * inv;
        const float4* vr = (const float4*)(vs + j * HD);
#pragma unroll
        for (int d = 0; d < 8; d++) {
            float4 vv = vr[d];
            o[d].x = fmaf(pj, vv.x, o[d].x);
            o[d].y = fmaf(pj, vv.y, o[d].y);
            o[d].z = fmaf(pj, vv.z, o[d].z);
            o[d].w = fmaf(pj, vv.w, o[d].w);
        }
    }

    float* og = g_o + ((size_t)n * NTOK + tid) * C_DIM + h * HD;
#pragma unroll
    for (int d = 0; d < 8; d++) ((float4*)og)[d] = o[d];
}

// ---------------------------------------------------------------------------
// Kernel C (TF32 MMA): proj GEMM + inverse window scatter.
// BM=128, BN=256 (full C), BK=8. grid = 2048 blocks.
// ---------------------------------------------------------------------------
__global__ __launch_bounds__(256) void proj_tc(
    const float* __restrict__ pb, float* __restrict__ out)
{
    __shared__ uint32_t As[2][128][APAD];
    __shared__ uint32_t Bs[2][8][BST];

    const int tid  = threadIdx.x;
    const int lane = tid & 31;
    const int warp = tid >> 5;
    const int wm   = warp >> 2;
    const int wn   = warp & 3;
    const int rbase = blockIdx.x * 128;

    const int arow = tid >> 1;
    const int akq  = tid & 1;
    const float* aptr = g_o + (size_t)(rbase + arow) * C_DIM + akq * 4;

    const int r0 = tid >> 6,         c0c = tid & 63;
    const int r1 = (tid + 256) >> 6;
    const uint32_t bs_s = (uint32_t)__cvta_generic_to_shared(Bs);
    const uint32_t bd0 = bs_s + (uint32_t)(r0 * BST + c0c * 4) * 4;
    const uint32_t bd1 = bs_s + (uint32_t)(r1 * BST + c0c * 4) * 4;
    const uint32_t bufB = 8 * BST * 4;
    const uint32_t* gb0 = g_pw + (size_t)r0 * 256 + c0c * 4;
    const uint32_t* gb1 = g_pw + (size_t)r1 * 256 + c0c * 4;

    float acc[4][8][4];
#pragma unroll
    for (int i = 0; i < 4; i++)
#pragma unroll
        for (int j = 0; j < 8; j++)
#pragma unroll
            for (int e = 0; e < 4; e++) acc[i][j][e] = 0.f;

    cp16(bd0, gb0);
    cp16(bd1, gb1);
    CP_COMMIT();
    {
        float4 av = *(const float4*)aptr;
        uint4 a4;
        a4.x = f2tf(av.x); a4.y = f2tf(av.y); a4.z = f2tf(av.z); a4.w = f2tf(av.w);
        *(uint4*)&As[0][arow][akq * 4] = a4;
    }
    CP_WAIT0();
    __syncthreads();

    int buf = 0;
    float4 av;
#pragma unroll 1
    for (int it = 0; it < 32; ++it) {
        if (it < 31) {
            const int k0 = (it + 1) * 8;
            const uint32_t boff = (buf ^ 1) * bufB;
            cp16(bd0 + boff, gb0 + (size_t)k0 * 256);
            cp16(bd1 + boff, gb1 + (size_t)k0 * 256);
            CP_COMMIT();
            av = *(const float4*)(aptr + k0);
        }

        const int t = lane & 3, g = lane >> 2;
        uint32_t afr[4][4];
#pragma unroll
        for (int mf = 0; mf < 4; mf++) {
            const int r = wm * 64 + mf * 16 + g;
            afr[mf][0] = As[buf][r][t];
            afr[mf][1] = As[buf][r + 8][t];
            afr[mf][2] = As[buf][r][t + 4];
            afr[mf][3] = As[buf][r + 8][t + 4];
        }
        uint32_t bfr[8][2];
#pragma unroll
        for (int nf = 0; nf < 8; nf++) {
            const int nn = wn * 64 + nf * 8 + g;
            bfr[nf][0] = Bs[buf][t][nn];
            bfr[nf][1] = Bs[buf][t + 4][nn];
        }
#pragma unroll
        for (int mf = 0; mf < 4; mf++)
#pragma unroll
            for (int nf = 0; nf < 8; nf++)
                mma8(acc[mf][nf], afr[mf], bfr[nf]);

        if (it < 31) {
            uint4 a4;
            a4.x = f2tf(av.x); a4.y = f2tf(av.y); a4.z = f2tf(av.z); a4.w = f2tf(av.w);
            *(uint4*)&As[buf ^ 1][arow][akq * 4] = a4;
            CP_WAIT0();
        }
        __syncthreads();
        buf ^= 1;
    }

    // Epilogue: + proj_b, inverse window scatter to (t,h,w,c)
#pragma unroll
    for (int mf = 0; mf < 4; mf++) {
        const int row0 = wm * 64 + mf * 16 + (lane >> 2);
#pragma unroll
        for (int nf = 0; nf < 8; nf++) {
            const int col = wn * 64 + nf * 8 + (lane & 3) * 2;
            const float b0 = pb[col], b1 = pb[col + 1];
            const float* c4 = acc[mf][nf];
#pragma unroll
            for (int half = 0; half < 2; half++) {
                const int grow = rbase + row0 + half * 8;
                const int win = grow >> 6;
                const int p   = grow & 63;
                const int t_idx = win >> 10, wh = (win >> 5) & 31, ww = win & 31;
                const int py = p >> 3, px = p & 7;
                const size_t pix =
                    (((size_t)t_idx * H_DIM + wh * PS + py) * W_DIM + ww * PS + px) * C_DIM;
                float2 v2;
                v2.x = c4[half * 2 + 0] + b0;
                v2.y = c4[half * 2 + 1] + b1;
                *(float2*)(out + pix + col) = v2;
            }
        }
    }
}

// ---------------------------------------------------------------------------
extern "C" void kernel_launch(void* const* d_in, const int* in_sizes, int n_in,
                              void* d_out, int out_size)
{
    const float* vid  = (const float*)d_in[0];
    const float* modu = (const float*)d_in[1];
    const float* wq   = (const float*)d_in[2];
    const float* bq   = (const float*)d_in[3];
    const float* wkv  = (const float*)d_in[4];
    const float* bkv  = (const float*)d_in[5];
    const float* pw   = (const float*)d_in[6];
    const float* pb   = (const float*)d_in[7];
    const float* rpt  = (const float*)d_in[8];
    float* out = (float*)d_out;

    prep_kernel<<<1024, 256>>>(wq, bq, wkv, bkv, pw);
    qkv_tc<<<dim3(3, 2048), 256>>>(vid, modu);
    attn_kernel<<<NWIN * NH, 64>>>(rpt);
    proj_tc<<<2048, 256>>>(pb, out);
}

// round 5
// speedup vs baseline: 2.1701x; 1.0116x over previous
#include <cuda_runtime.h>
#include <math.h>
#include <stdint.h>

// Problem constants
#define T_DIM   4
#define H_DIM   256
#define W_DIM   256
#define C_DIM   256
#define PS      8
#define NH      8
#define HD      32
#define NTOK    64
#define NWIN    4096
#define NROWS   (NWIN * NTOK)
#define VID_ELEMS ((size_t)T_DIM * H_DIM * W_DIM * C_DIM)  // 67108864

// Scratch (allocation-free rule: __device__ globals)
__device__ float    g_q[(size_t)NWIN * NH * NTOK * HD]; // [n][h][p][d]
__device__ float    g_k[(size_t)NWIN * NH * NTOK * HD];
__device__ float    g_v[(size_t)NWIN * NH * NTOK * HD];
__device__ uint32_t g_o[(size_t)NROWS * C_DIM];         // tf32 [n][p][c]
__device__ uint32_t g_vt[VID_ELEMS];                    // tf32 vid
__device__ uint32_t g_wb[256 * 768];                    // tf32 [k][n]: [wq*sc | wkv]
__device__ uint32_t g_pw[256 * 256];                    // tf32 [k][n]: proj_w
__device__ float    g_mw[64 * 768];                     // fp32: modu@W + bias (q part scaled)

// ---------------------------------------------------------------------------
__device__ __forceinline__ uint32_t f2tf(float x) {
    uint32_t r;
    asm("cvt.rna.tf32.f32 %0, %1;" : "=r"(r) : "f"(x));
    return r;
}
__device__ __forceinline__ void mma8(float* c, const uint32_t* a, const uint32_t* b) {
    asm volatile(
        "mma.sync.aligned.m16n8k8.row.col.f32.tf32.tf32.f32 "
        "{%0,%1,%2,%3}, {%4,%5,%6,%7}, {%8,%9}, {%0,%1,%2,%3};"
        : "+f"(c[0]), "+f"(c[1]), "+f"(c[2]), "+f"(c[3])
        : "r"(a[0]), "r"(a[1]), "r"(a[2]), "r"(a[3]), "r"(b[0]), "r"(b[1]));
}
__device__ __forceinline__ void cp16(uint32_t s, const void* g) {
    asm volatile("cp.async.ca.shared.global [%0], [%1], 16;" :: "r"(s), "l"(g));
}
#define CP_COMMIT() asm volatile("cp.async.commit_group;")
#define CP_WAIT0()  asm volatile("cp.async.wait_group 0;")

#define APAD 20     // A k-stride (words): frag banks (20g + t) all distinct; rows 16B-aligned
#define BST  136    // B n-stride (words): 136 mod 32 = 8 -> banks (8t + g) all distinct

// ---------------------------------------------------------------------------
// Prep 1: weights -> tf32 (q-scale folded into wq columns)
// ---------------------------------------------------------------------------
__global__ __launch_bounds__(256) void prep_w(
    const float* __restrict__ wq, const float* __restrict__ wkv,
    const float* __restrict__ pw)
{
    const float sc = 0.1767766952966369f; // 1/sqrt(32)
    int idx = blockIdx.x * 256 + threadIdx.x;
    if (idx < 196608) {
        int k = idx / 768, c = idx % 768;
        float v = (c < 256) ? wq[k * 256 + c] * sc : wkv[k * 512 + (c - 256)];
        g_wb[idx] = f2tf(v);
    } else {
        int j = idx - 196608;
        g_pw[j] = f2tf(pw[j]);
    }
}

// ---------------------------------------------------------------------------
// Prep 2: vid -> tf32 (streaming)
// ---------------------------------------------------------------------------
__global__ __launch_bounds__(256) void prep_vid(const float* __restrict__ vid)
{
    size_t i = ((size_t)blockIdx.x * 256 + threadIdx.x) * 4;
    float4 v = *(const float4*)(vid + i);
    uint4 o;
    o.x = f2tf(v.x); o.y = f2tf(v.y); o.z = f2tf(v.z); o.w = f2tf(v.w);
    *(uint4*)(g_vt + i) = o;
}

// ---------------------------------------------------------------------------
// Prep 3: modw[p][c] = modu[p]@W col c (+ bias, q part scaled). grid 64 x 256.
// ---------------------------------------------------------------------------
__global__ __launch_bounds__(256) void prep_modw(
    const float* __restrict__ modu,
    const float* __restrict__ wq,  const float* __restrict__ bq,
    const float* __restrict__ wkv, const float* __restrict__ bkv)
{
    __shared__ float m[256];
    const int p = blockIdx.x;
    m[threadIdx.x] = modu[p * 256 + threadIdx.x];
    __syncthreads();
    const float sc = 0.1767766952966369f;
#pragma unroll
    for (int rep = 0; rep < 3; rep++) {
        int c = rep * 256 + threadIdx.x;
        float s = 0.f;
        if (c < 256) {
            for (int k = 0; k < 256; k++) s = fmaf(m[k], wq[k * 256 + c], s);
            s = (s + bq[c]) * sc;
        } else {
            int cc = c - 256;
            for (int k = 0; k < 256; k++) s = fmaf(m[k], wkv[k * 512 + cc], s);
            s += bkv[cc];
        }
        g_mw[p * 768 + c] = s;
    }
}

// ---------------------------------------------------------------------------
// Kernel A (TF32 MMA): X @ [wq|wkv]; A = g_vt (gathered by window rows).
// BM=128 (2 windows), BN=128, BK=16 double-buffered. 8 warps (2m x 4n),
// warp tile 64x32. grid = (6, 2048).
// ---------------------------------------------------------------------------
__global__ __launch_bounds__(256, 2) void qkv_tc()
{
    __shared__ uint32_t As[2][128][APAD];
    __shared__ uint32_t Bs[2][16][BST];

    const int tid  = threadIdx.x;
    const int lane = tid & 31;
    const int warp = tid >> 5;
    const int wm   = warp >> 2;       // rows wm*64
    const int wn   = warp & 3;        // cols wn*32
    const int n2   = blockIdx.y * 2;  // first window
    const int n0   = blockIdx.x * 128;

    // A cp.async mapping: row = tid>>1 (0..127), two cp16 at word offsets c0, c0+4
    const int arow = tid >> 1;
    const int ac0  = (tid & 1) * 8;
    const int wgt  = n2 + (arow >> 6);
    const int p    = arow & 63;
    const int t_idx = wgt >> 10, wh = (wgt >> 5) & 31, ww = wgt & 31;
    const int py = p >> 3, px = p & 7;
    const uint32_t* aptr = g_vt +
        (((size_t)t_idx * H_DIM + wh * PS + py) * W_DIM + ww * PS + px) * C_DIM + ac0;
    const uint32_t smem_a = (uint32_t)__cvta_generic_to_shared(As);
    const uint32_t ad = smem_a + (uint32_t)(arow * APAD + ac0) * 4;
    const uint32_t bufA = 128 * APAD * 4;

    // B cp.async mapping: row = tid>>4 (0..15), cols (tid&15)*8
    const int br = tid >> 4;
    const int bc = (tid & 15) * 8;
    const uint32_t* bptr = g_wb + (size_t)br * 768 + n0 + bc;
    const uint32_t smem_b = (uint32_t)__cvta_generic_to_shared(Bs);
    const uint32_t bd = smem_b + (uint32_t)(br * BST + bc) * 4;
    const uint32_t bufB = 16 * BST * 4;

    float acc[4][4][4];
#pragma unroll
    for (int i = 0; i < 4; i++)
#pragma unroll
        for (int j = 0; j < 4; j++)
#pragma unroll
            for (int e = 0; e < 4; e++) acc[i][j][e] = 0.f;

    // Prologue: stage 0
    cp16(ad, aptr);         cp16(ad + 16, aptr + 4);
    cp16(bd, bptr);         cp16(bd + 16, bptr + 4);
    CP_COMMIT();

    int buf = 0;
#pragma unroll 1
    for (int it = 0; it < 16; ++it) {
        CP_WAIT0();
        __syncthreads();
        if (it < 15) {
            const int k0 = (it + 1) * 16;
            const uint32_t oa = (buf ^ 1) * bufA, ob = (buf ^ 1) * bufB;
            cp16(ad + oa, aptr + k0);          cp16(ad + oa + 16, aptr + k0 + 4);
            cp16(bd + ob, bptr + (size_t)k0 * 768);
            cp16(bd + ob + 16, bptr + (size_t)k0 * 768 + 4);
            CP_COMMIT();
        }

        const int t = lane & 3, g = lane >> 2;
#pragma unroll
        for (int ks = 0; ks < 2; ks++) {
            const int c = ks * 8 + t;
            uint32_t afr[4][4];
#pragma unroll
            for (int mf = 0; mf < 4; mf++) {
                const int r = wm * 64 + mf * 16 + g;
                afr[mf][0] = As[buf][r][c];
                afr[mf][1] = As[buf][r + 8][c];
                afr[mf][2] = As[buf][r][c + 4];
                afr[mf][3] = As[buf][r + 8][c + 4];
            }
            uint32_t bfr[4][2];
#pragma unroll
            for (int nf = 0; nf < 4; nf++) {
                const int nn = wn * 32 + nf * 8 + g;
                bfr[nf][0] = Bs[buf][c][nn];
                bfr[nf][1] = Bs[buf][c + 4][nn];
            }
#pragma unroll
            for (int mf = 0; mf < 4; mf++)
#pragma unroll
                for (int nf = 0; nf < 4; nf++)
                    mma8(acc[mf][nf], afr[mf], bfr[nf]);
        }
        __syncthreads();
        buf ^= 1;
    }

    // Epilogue: + modw (modulator term incl. bias), scatter to [n][h][p][d]
    const int seg = n0 >> 8;                 // 0:q 1:k 2:v
    float* dst = (seg == 0) ? g_q : (seg == 1) ? g_k : g_v;
#pragma unroll
    for (int mf = 0; mf < 4; mf++) {
        const int row0 = wm * 64 + mf * 16 + (lane >> 2);
#pragma unroll
        for (int nf = 0; nf < 4; nf++) {
            const int clg = n0 + wn * 32 + nf * 8 + (lane & 3) * 2;  // global col
            const int cc  = clg & 255;
            const int hh  = cc >> 5, d0 = cc & 31;
            const float* c4 = acc[mf][nf];
#pragma unroll
            for (int half = 0; half < 2; half++) {
                const int row = row0 + half * 8;
                const int win = n2 + (row >> 6);
                const int pp  = row & 63;
                const float2 mwv = *(const float2*)(g_mw + pp * 768 + clg);
                float2 v2;
                v2.x = c4[half * 2 + 0] + mwv.x;
                v2.y = c4[half * 2 + 1] + mwv.y;
                *(float2*)(dst + (((size_t)win * NH + hh) * NTOK + pp) * HD + d0) = v2;
            }
        }
    }
}

// ---------------------------------------------------------------------------
// Kernel B: attention per (window, head). 64 threads = 64 query rows.
// Fully unrolled so s[] stays in registers. Output stored as tf32.
// ---------------------------------------------------------------------------
__global__ __launch_bounds__(64) void attn_kernel(const float* __restrict__ rpt)
{
    __shared__ float ks[NTOK * HD];
    __shared__ float vs[NTOK * HD];
    __shared__ float bs[225];

    const int b = blockIdx.x;
    const int h = b & 7;
    const int n = b >> 3;
    const int tid = threadIdx.x;
    const size_t base = (size_t)b * (NTOK * HD);

    const float4* kg = (const float4*)(g_k + base);
    const float4* vg = (const float4*)(g_v + base);
    float4* ks4 = (float4*)ks;
    float4* vs4 = (float4*)vs;
#pragma unroll
    for (int i = tid; i < NTOK * HD / 4; i += 64) { ks4[i] = kg[i]; vs4[i] = vg[i]; }
    for (int i = tid; i < 225; i += 64) bs[i] = rpt[(size_t)i * NH + h];
    __syncthreads();

    float4 q[8];
    const float4* qg = (const float4*)(g_q + base + (size_t)tid * HD);
#pragma unroll
    for (int i = 0; i < 8; i++) q[i] = qg[i];

    const int qy = tid >> 3, qx = tid & 7;

    float s[64];
    float mx = -1e30f;
#pragma unroll
    for (int j = 0; j < 64; j++) {
        float acc = 0.f;
        const float4* kr = (const float4*)(ks + j * HD);
#pragma unroll
        for (int d = 0; d < 8; d++) {
            float4 kv = kr[d];
            acc = fmaf(q[d].x, kv.x, acc);
            acc = fmaf(q[d].y, kv.y, acc);
            acc = fmaf(q[d].z, kv.z, acc);
            acc = fmaf(q[d].w, kv.w, acc);
        }
        const int ky = j >> 3, kx = j & 7;
        acc += bs[(qy - ky + 7) * 15 + (qx - kx + 7)];
        s[j] = acc;
        mx = fmaxf(mx, acc);
    }

    float sum = 0.f;
#pragma unroll
    for (int j = 0; j < 64; j++) {
        float e = __expf(s[j] - mx);
        s[j] = e;
        sum += e;
    }
    const float inv = 1.0f / sum;

    float4 o[8];
#pragma unroll
    for (int d = 0; d < 8; d++) { o[d].x = o[d].y = o[d].z = o[d].w = 0.f; }
#pragma unroll
    for (int j = 0; j < 64; j++) {
        const float pj = s[j] * inv;
        const float4* vr = (const float4*)(vs + j * HD);
#pragma unroll
        for (int d = 0; d < 8; d++) {
            float4 vv = vr[d];
            o[d].x = fmaf(pj, vv.x, o[d].x);
            o[d].y = fmaf(pj, vv.y, o[d].y);
            o[d].z = fmaf(pj, vv.z, o[d].z);
            o[d].w = fmaf(pj, vv.w, o[d].w);
        }
    }

    uint32_t* og = g_o + ((size_t)n * NTOK + tid) * C_DIM + h * HD;
#pragma unroll
    for (int d = 0; d < 8; d++) {
        uint4 u;
        u.x = f2tf(o[d].x); u.y = f2tf(o[d].y);
        u.z = f2tf(o[d].z); u.w = f2tf(o[d].w);
        ((uint4*)og)[d] = u;
    }
}

// ---------------------------------------------------------------------------
// Kernel C (TF32 MMA): proj GEMM (g_o tf32 @ g_pw) + inverse window scatter.
// BM=128, BN=128, BK=16. grid = (2, 2048).
// ---------------------------------------------------------------------------
__global__ __launch_bounds__(256, 2) void proj_tc(
    const float* __restrict__ pb, float* __restrict__ out)
{
    __shared__ uint32_t As[2][128][APAD];
    __shared__ uint32_t Bs[2][16][BST];

    const int tid  = threadIdx.x;
    const int lane = tid & 31;
    const int warp = tid >> 5;
    const int wm   = warp >> 2;
    const int wn   = warp & 3;
    const int rbase = blockIdx.y * 128;
    const int n0    = blockIdx.x * 128;

    const int arow = tid >> 1;
    const int ac0  = (tid & 1) * 8;
    const uint32_t* aptr = g_o + (size_t)(rbase + arow) * C_DIM + ac0;
    const uint32_t smem_a = (uint32_t)__cvta_generic_to_shared(As);
    const uint32_t ad = smem_a + (uint32_t)(arow * APAD + ac0) * 4;
    const uint32_t bufA = 128 * APAD * 4;

    const int br = tid >> 4;
    const int bc = (tid & 15) * 8;
    const uint32_t* bptr = g_pw + (size_t)br * 256 + n0 + bc;
    const uint32_t smem_b = (uint32_t)__cvta_generic_to_shared(Bs);
    const uint32_t bd = smem_b + (uint32_t)(br * BST + bc) * 4;
    const uint32_t bufB = 16 * BST * 4;

    float acc[4][4][4];
#pragma unroll
    for (int i = 0; i < 4; i++)
#pragma unroll
        for (int j = 0; j < 4; j++)
#pragma unroll
            for (int e = 0; e < 4; e++) acc[i][j][e] = 0.f;

    cp16(ad, aptr);        cp16(ad + 16, aptr + 4);
    cp16(bd, bptr);        cp16(bd + 16, bptr + 4);
    CP_COMMIT();

    int buf = 0;
#pragma unroll 1
    for (int it = 0; it < 16; ++it) {
        CP_WAIT0();
        __syncthreads();
        if (it < 15) {
            const int k0 = (it + 1) * 16;
            const uint32_t oa = (buf ^ 1) * bufA, ob = (buf ^ 1) * bufB;
            cp16(ad + oa, aptr + k0);          cp16(ad + oa + 16, aptr + k0 + 4);
            cp16(bd + ob, bptr + (size_t)k0 * 256);
            cp16(bd + ob + 16, bptr + (size_t)k0 * 256 + 4);
            CP_COMMIT();
        }

        const int t = lane & 3, g = lane >> 2;
#pragma unroll
        for (int ks = 0; ks < 2; ks++) {
            const int c = ks * 8 + t;
            uint32_t afr[4][4];
#pragma unroll
            for (int mf = 0; mf < 4; mf++) {
                const int r = wm * 64 + mf * 16 + g;
                afr[mf][0] = As[buf][r][c];
                afr[mf][1] = As[buf][r + 8][c];
                afr[mf][2] = As[buf][r][c + 4];
                afr[mf][3] = As[buf][r + 8][c + 4];
            }
            uint32_t bfr[4][2];
#pragma unroll
            for (int nf = 0; nf < 4; nf++) {
                const int nn = wn * 32 + nf * 8 + g;
                bfr[nf][0] = Bs[buf][c][nn];
                bfr[nf][1] = Bs[buf][c + 4][nn];
            }
#pragma unroll
            for (int mf = 0; mf < 4; mf++)
#pragma unroll
                for (int nf = 0; nf < 4; nf++)
                    mma8(acc[mf][nf], afr[mf], bfr[nf]);
        }
        __syncthreads();
        buf ^= 1;
    }

    // Epilogue: + proj_b, inverse window scatter to (t,h,w,c)
#pragma unroll
    for (int mf = 0; mf < 4; mf++) {
        const int row0 = wm * 64 + mf * 16 + (lane >> 2);
#pragma unroll
        for (int nf = 0; nf < 4; nf++) {
            const int col = n0 + wn * 32 + nf * 8 + (lane & 3) * 2;
            const float b0 = pb[col], b1 = pb[col + 1];
            const float* c4 = acc[mf][nf];
#pragma unroll
            for (int half = 0; half < 2; half++) {
                const int grow = rbase + row0 + half * 8;
                const int win = grow >> 6;
                const int p   = grow & 63;
                const int t_idx = win >> 10, wh = (win >> 5) & 31, ww = win & 31;
                const int py = p >> 3, px = p & 7;
                const size_t pix =
                    (((size_t)t_idx * H_DIM + wh * PS + py) * W_DIM + ww * PS + px) * C_DIM;
                float2 v2;
                v2.x = c4[half * 2 + 0] + b0;
                v2.y = c4[half * 2 + 1] + b1;
                *(float2*)(out + pix + col) = v2;
            }
        }
    }
}

// ---------------------------------------------------------------------------
extern "C" void kernel_launch(void* const* d_in, const int* in_sizes, int n_in,
                              void* d_out, int out_size)
{
    const float* vid  = (const float*)d_in[0];
    const float* modu = (const float*)d_in[1];
    const float* wq   = (const float*)d_in[2];
    const float* bq   = (const float*)d_in[3];
    const float* wkv  = (const float*)d_in[4];
    const float* bkv  = (const float*)d_in[5];
    const float* pw   = (const float*)d_in[6];
    const float* pb   = (const float*)d_in[7];
    const float* rpt  = (const float*)d_in[8];
    float* out = (float*)d_out;

    prep_w<<<1024, 256>>>(wq, wkv, pw);
    prep_vid<<<65536, 256>>>(vid);
    prep_modw<<<64, 256>>>(modu, wq, bq, wkv, bkv);
    qkv_tc<<<dim3(6, 2048), 256>>>();
    attn_kernel<<<NWIN * NH, 64>>>(rpt);
    proj_tc<<<dim3(2, 2048), 256>>>(pb, out);
}

// round 7
// speedup vs baseline: 2.1780x; 1.0036x over previous
#include <cuda_runtime.h>
#include <math.h>
#include <stdint.h>

// Problem constants
#define T_DIM   4
#define H_DIM   256
#define W_DIM   256
#define C_DIM   256
#define PS      8
#define NH      8
#define HD      32
#define NTOK    64
#define NWIN    4096
#define NROWS   (NWIN * NTOK)
#define VID_ELEMS ((size_t)T_DIM * H_DIM * W_DIM * C_DIM)

// Scratch (allocation-free rule: __device__ globals)
__device__ float    g_q[(size_t)NWIN * NH * NTOK * HD]; // [n][h][p][d]
__device__ float    g_k[(size_t)NWIN * NH * NTOK * HD];
__device__ float    g_v[(size_t)NWIN * NH * NTOK * HD];
__device__ uint32_t g_o[(size_t)NROWS * C_DIM];         // tf32 [n][p][c]
__device__ uint32_t g_vt[VID_ELEMS];                    // tf32 vid
__device__ uint32_t g_wb[256 * 768];                    // tf32 [k][n]: [wq*sc | wkv]
__device__ uint32_t g_pw[256 * 256];                    // tf32 [k][n]: proj_w
__device__ float    g_mw[64 * 768];                     // fp32: modu@W + bias (q scaled)

// ---------------------------------------------------------------------------
__device__ __forceinline__ uint32_t f2tf(float x) {
    uint32_t r;
    asm("cvt.rna.tf32.f32 %0, %1;" : "=r"(r) : "f"(x));
    return r;
}
__device__ __forceinline__ void mma8(float* c, const uint32_t* a, const uint32_t* b) {
    asm volatile(
        "mma.sync.aligned.m16n8k8.row.col.f32.tf32.tf32.f32 "
        "{%0,%1,%2,%3}, {%4,%5,%6,%7}, {%8,%9}, {%0,%1,%2,%3};"
        : "+f"(c[0]), "+f"(c[1]), "+f"(c[2]), "+f"(c[3])
        : "r"(a[0]), "r"(a[1]), "r"(a[2]), "r"(a[3]), "r"(b[0]), "r"(b[1]));
}
__device__ __forceinline__ void cp16(uint32_t s, const void* g) {
    asm volatile("cp.async.ca.shared.global [%0], [%1], 16;" :: "r"(s), "l"(g));
}
#define CP_COMMIT() asm volatile("cp.async.commit_group;" ::: "memory")
#define CP_WAIT(n)  asm volatile("cp.async.wait_group %0;" :: "n"(n) : "memory")

#define APAD 20     // A k-stride (words): frag banks (20g + t) all distinct
#define BST  136    // B n-stride (words): 136 mod 32 = 8 -> banks (8t + g) all distinct
#define NSTG 3
// Dynamic smem layout (bytes)
#define A_STG   (128 * APAD * 4)       // 10240
#define B_STG   (16 * BST * 4)         // 8704
#define B_BASE  (NSTG * A_STG)         // 30720
#define SMEM_DYN (B_BASE + NSTG * B_STG)   // 56832

// ---------------------------------------------------------------------------
// Prep 1: weights -> tf32 (q-scale folded into wq columns)
// ---------------------------------------------------------------------------
__global__ __launch_bounds__(256) void prep_w(
    const float* __restrict__ wq, const float* __restrict__ wkv,
    const float* __restrict__ pw)
{
    const float sc = 0.1767766952966369f; // 1/sqrt(32)
    int idx = blockIdx.x * 256 + threadIdx.x;
    if (idx < 196608) {
        int k = idx / 768, c = idx % 768;
        float v = (c < 256) ? wq[k * 256 + c] * sc : wkv[k * 512 + (c - 256)];
        g_wb[idx] = f2tf(v);
    } else {
        int j = idx - 196608;
        g_pw[j] = f2tf(pw[j]);
    }
}

// ---------------------------------------------------------------------------
// Prep 2: vid -> tf32 (streaming)
// ---------------------------------------------------------------------------
__global__ __launch_bounds__(256) void prep_vid(const float* __restrict__ vid)
{
    size_t i = ((size_t)blockIdx.x * 256 + threadIdx.x) * 4;
    float4 v = *(const float4*)(vid + i);
    uint4 o;
    o.x = f2tf(v.x); o.y = f2tf(v.y); o.z = f2tf(v.z); o.w = f2tf(v.w);
    *(uint4*)(g_vt + i) = o;
}

// ---------------------------------------------------------------------------
// Prep 3: modw[p][c] = modu[p]@W col c (+ bias, q part scaled). grid 64 x 256.
// ---------------------------------------------------------------------------
__global__ __launch_bounds__(256) void prep_modw(
    const float* __restrict__ modu,
    const float* __restrict__ wq,  const float* __restrict__ bq,
    const float* __restrict__ wkv, const float* __restrict__ bkv)
{
    __shared__ float m[256];
    const int p = blockIdx.x;
    m[threadIdx.x] = modu[p * 256 + threadIdx.x];
    __syncthreads();
    const float sc = 0.1767766952966369f;
#pragma unroll
    for (int rep = 0; rep < 3; rep++) {
        int c = rep * 256 + threadIdx.x;
        float s = 0.f;
        if (c < 256) {
            for (int k = 0; k < 256; k++) s = fmaf(m[k], wq[k * 256 + c], s);
            s = (s + bq[c]) * sc;
        } else {
            int cc = c - 256;
            for (int k = 0; k < 256; k++) s = fmaf(m[k], wkv[k * 512 + cc], s);
            s += bkv[cc];
        }
        g_mw[p * 768 + c] = s;
    }
}

// ---------------------------------------------------------------------------
// Kernel A (TF32 MMA): X @ [wq|wkv]; A = g_vt. BM=128 (2 windows), BN=128,
// BK=16, 3-stage cp.async pipeline. 8 warps (2m x 4n), warp tile 64x32.
// grid = (6, 2048).
// ---------------------------------------------------------------------------
__global__ __launch_bounds__(256, 2) void qkv_tc()
{
    extern __shared__ uint32_t smem[];
    uint32_t (*As)[128][APAD] = (uint32_t(*)[128][APAD])smem;
    uint32_t (*Bs)[16][BST]   = (uint32_t(*)[16][BST])(smem + B_BASE / 4);
    const uint32_t su = (uint32_t)__cvta_generic_to_shared(smem);

    const int tid  = threadIdx.x;
    const int lane = tid & 31;
    const int warp = tid >> 5;
    const int wm   = warp >> 2;       // rows wm*64
    const int wn   = warp & 3;        // cols wn*32
    const int n2   = blockIdx.y * 2;  // first window
    const int n0   = blockIdx.x * 128;

    // A cp.async mapping: row = tid>>1 (0..127), two cp16 at word cols ac0, ac0+4
    const int arow = tid >> 1;
    const int ac0  = (tid & 1) * 8;
    const int wgt  = n2 + (arow >> 6);
    const int p    = arow & 63;
    const int t_idx = wgt >> 10, wh = (wgt >> 5) & 31, ww = wgt & 31;
    const int py = p >> 3, px = p & 7;
    const uint32_t* aptr = g_vt +
        (((size_t)t_idx * H_DIM + wh * PS + py) * W_DIM + ww * PS + px) * C_DIM + ac0;
    const uint32_t ad = su + (uint32_t)(arow * APAD + ac0) * 4;

    // B cp.async mapping: row = tid>>4 (0..15), cols (tid&15)*8
    const int br = tid >> 4;
    const int bc = (tid & 15) * 8;
    const uint32_t* bptr = g_wb + (size_t)br * 768 + n0 + bc;
    const uint32_t bd = su + B_BASE + (uint32_t)(br * BST + bc) * 4;

    float acc[4][4][4];
#pragma unroll
    for (int i = 0; i < 4; i++)
#pragma unroll
        for (int j = 0; j < 4; j++)
#pragma unroll
            for (int e = 0; e < 4; e++) acc[i][j][e] = 0.f;

    // Prologue: stages 0,1 (ktiles 0,1)
#pragma unroll
    for (int s = 0; s < 2; s++) {
        const int k0 = s * 16;
        cp16(ad + s * A_STG, aptr + k0);  cp16(ad + s * A_STG + 16, aptr + k0 + 4);
        cp16(bd + s * B_STG, bptr + (size_t)k0 * 768);
        cp16(bd + s * B_STG + 16, bptr + (size_t)k0 * 768 + 4);
        CP_COMMIT();
    }

#pragma unroll 1
    for (int kt = 0; kt < 16; ++kt) {
        if (kt < 14) CP_WAIT(1); else CP_WAIT(0);
        __syncthreads();            // stage kt%3 visible; all warps done with stage (kt+2)%3
        if (kt + 2 < 16) {
            const int s = (kt + 2) % NSTG;
            const int k0 = (kt + 2) * 16;
            cp16(ad + s * A_STG, aptr + k0);  cp16(ad + s * A_STG + 16, aptr + k0 + 4);
            cp16(bd + s * B_STG, bptr + (size_t)k0 * 768);
            cp16(bd + s * B_STG + 16, bptr + (size_t)k0 * 768 + 4);
            CP_COMMIT();
        }

        const int buf = kt % NSTG;
        const int t = lane & 3, g = lane >> 2;
#pragma unroll
        for (int ks = 0; ks < 2; ks++) {
            const int c = ks * 8 + t;
            uint32_t afr[4][4];
#pragma unroll
            for (int mf = 0; mf < 4; mf++) {
                const int r = wm * 64 + mf * 16 + g;
                afr[mf][0] = As[buf][r][c];
                afr[mf][1] = As[buf][r + 8][c];
                afr[mf][2] = As[buf][r][c + 4];
                afr[mf][3] = As[buf][r + 8][c + 4];
            }
            uint32_t bfr[4][2];
#pragma unroll
            for (int nf = 0; nf < 4; nf++) {
                const int nn = wn * 32 + nf * 8 + g;
                bfr[nf][0] = Bs[buf][c][nn];
                bfr[nf][1] = Bs[buf][c + 4][nn];
            }
#pragma unroll
            for (int mf = 0; mf < 4; mf++)
#pragma unroll
                for (int nf = 0; nf < 4; nf++)
                    mma8(acc[mf][nf], afr[mf], bfr[nf]);
        }
    }

    // Epilogue: + modw (modulator term incl. bias), scatter to [n][h][p][d]
    const int seg = n0 >> 8;                 // 0:q 1:k 2:v
    float* dst = (seg == 0) ? g_q : (seg == 1) ? g_k : g_v;
#pragma unroll
    for (int mf = 0; mf < 4; mf++) {
        const int row0 = wm * 64 + mf * 16 + (lane >> 2);
#pragma unroll
        for (int nf = 0; nf < 4; nf++) {
            const int clg = n0 + wn * 32 + nf * 8 + (lane & 3) * 2;  // global col
            const int cc  = clg & 255;
            const int hh  = cc >> 5, d0 = cc & 31;
            const float* c4 = acc[mf][nf];
#pragma unroll
            for (int half = 0; half < 2; half++) {
                const int row = row0 + half * 8;
                const int win = n2 + (row >> 6);
                const int pp  = row & 63;
                const float2 mwv = *(const float2*)(g_mw + pp * 768 + clg);
                float2 v2;
                v2.x = c4[half * 2 + 0] + mwv.x;
                v2.y = c4[half * 2 + 1] + mwv.y;
                *(float2*)(dst + (((size_t)win * NH + hh) * NTOK + pp) * HD + d0) = v2;
            }
        }
    }
}

// ---------------------------------------------------------------------------
// Kernel B: attention per (window, head). 64 threads = 64 query rows.
// ---------------------------------------------------------------------------
__global__ __launch_bounds__(64) void attn_kernel(const float* __restrict__ rpt)
{
    __shared__ float ks[NTOK * HD];
    __shared__ float vs[NTOK * HD];
    __shared__ float bs[225];

    const int b = blockIdx.x;
    const int h = b & 7;
    const int n = b >> 3;
    const int tid = threadIdx.x;
    const size_t base = (size_t)b * (NTOK * HD);

    const float4* kg = (const float4*)(g_k + base);
    const float4* vg = (const float4*)(g_v + base);
    float4* ks4 = (float4*)ks;
    float4* vs4 = (float4*)vs;
#pragma unroll
    for (int i = tid; i < NTOK * HD / 4; i += 64) { ks4[i] = kg[i]; vs4[i] = vg[i]; }
    for (int i = tid; i < 225; i += 64) bs[i] = rpt[(size_t)i * NH + h];
    __syncthreads();

    float4 q[8];
    const float4* qg = (const float4*)(g_q + base + (size_t)tid * HD);
#pragma unroll
    for (int i = 0; i < 8; i++) q[i] = qg[i];

    const int qy = tid >> 3, qx = tid & 7;

    float s[64];
    float mx = -1e30f;
#pragma unroll
    for (int j = 0; j < 64; j++) {
        float acc = 0.f;
        const float4* kr = (const float4*)(ks + j * HD);
#pragma unroll
        for (int d = 0; d < 8; d++) {
            float4 kv = kr[d];
            acc = fmaf(q[d].x, kv.x, acc);
            acc = fmaf(q[d].y, kv.y, acc);
            acc = fmaf(q[d].z, kv.z, acc);
            acc = fmaf(q[d].w, kv.w, acc);
        }
        const int ky = j >> 3, kx = j & 7;
        acc += bs[(qy - ky + 7) * 15 + (qx - kx + 7)];
        s[j] = acc;
        mx = fmaxf(mx, acc);
    }

    float sum = 0.f;
#pragma unroll
    for (int j = 0; j < 64; j++) {
        float e = __expf(s[j] - mx);
        s[j] = e;
        sum += e;
    }
    const float inv = 1.0f / sum;

    float4 o[8];
#pragma unroll
    for (int d = 0; d < 8; d++) { o[d].x = o[d].y = o[d].z = o[d].w = 0.f; }
#pragma unroll
    for (int j = 0; j < 64; j++) {
        const float pj = s[j] * inv;
        const float4* vr = (const float4*)(vs + j * HD);
#pragma unroll
        for (int d = 0; d < 8; d++) {
            float4 vv = vr[d];
            o[d].x = fmaf(pj, vv.x, o[d].x);
            o[d].y = fmaf(pj, vv.y, o[d].y);
            o[d].z = fmaf(pj, vv.z, o[d].z);
            o[d].w = fmaf(pj, vv.w, o[d].w);
        }
    }

    uint32_t* og = g_o + ((size_t)n * NTOK + tid) * C_DIM + h * HD;
#pragma unroll
    for (int d = 0; d < 8; d++) {
        uint4 u;
        u.x = f2tf(o[d].x); u.y = f2tf(o[d].y);
        u.z = f2tf(o[d].z); u.w = f2tf(o[d].w);
        ((uint4*)og)[d] = u;
    }
}

// ---------------------------------------------------------------------------
// Kernel C (TF32 MMA): proj GEMM (g_o tf32 @ g_pw) + inverse window scatter.
// Same 3-stage pipeline. grid = (2, 2048).
// ---------------------------------------------------------------------------
__global__ __launch_bounds__(256, 2) void proj_tc(
    const float* __restrict__ pb, float* __restrict__ out)
{
    extern __shared__ uint32_t smem[];
    uint32_t (*As)[128][APAD] = (uint32_t(*)[128][APAD])smem;
    uint32_t (*Bs)[16][BST]   = (uint32_t(*)[16][BST])(smem + B_BASE / 4);
    const uint32_t su = (uint32_t)__cvta_generic_to_shared(smem);

    const int tid  = threadIdx.x;
    const int lane = tid & 31;
    const int warp = tid >> 5;
    const int wm   = warp >> 2;
    const int wn   = warp & 3;
    const int rbase = blockIdx.y * 128;
    const int n0    = blockIdx.x * 128;

    const int arow = tid >> 1;
    const int ac0  = (tid & 1) * 8;
    const uint32_t* aptr = g_o + (size_t)(rbase + arow) * C_DIM + ac0;
    const uint32_t ad = su + (uint32_t)(arow * APAD + ac0) * 4;

    const int br = tid >> 4;
    const int bc = (tid & 15) * 8;
    const uint32_t* bptr = g_pw + (size_t)br * 256 + n0 + bc;
    const uint32_t bd = su + B_BASE + (uint32_t)(br * BST + bc) * 4;

    float acc[4][4][4];
#pragma unroll
    for (int i = 0; i < 4; i++)
#pragma unroll
        for (int j = 0; j < 4; j++)
#pragma unroll
            for (int e = 0; e < 4; e++) acc[i][j][e] = 0.f;

#pragma unroll
    for (int s = 0; s < 2; s++) {
        const int k0 = s * 16;
        cp16(ad + s * A_STG, aptr + k0);  cp16(ad + s * A_STG + 16, aptr + k0 + 4);
        cp16(bd + s * B_STG, bptr + (size_t)k0 * 256);
        cp16(bd + s * B_STG + 16, bptr + (size_t)k0 * 256 + 4);
        CP_COMMIT();
    }

#pragma unroll 1
    for (int kt = 0; kt < 16; ++kt) {
        if (kt < 14) CP_WAIT(1); else CP_WAIT(0);
        __syncthreads();
        if (kt + 2 < 16) {
            const int s = (kt + 2) % NSTG;
            const int k0 = (kt + 2) * 16;
            cp16(ad + s * A_STG, aptr + k0);  cp16(ad + s * A_STG + 16, aptr + k0 + 4);
            cp16(bd + s * B_STG, bptr + (size_t)k0 * 256);
            cp16(bd + s * B_STG + 16, bptr + (size_t)k0 * 256 + 4);
            CP_COMMIT();
        }

        const int buf = kt % NSTG;
        const int t = lane & 3, g = lane >> 2;
#pragma unroll
        for (int ks = 0; ks < 2; ks++) {
            const int c = ks * 8 + t;
            uint32_t afr[4][4];
#pragma unroll
            for (int mf = 0; mf < 4; mf++) {
                const int r = wm * 64 + mf * 16 + g;
                afr[mf][0] = As[buf][r][c];
                afr[mf][1] = As[buf][r + 8][c];
                afr[mf][2] = As[buf][r][c + 4];
                afr[mf][3] = As[buf][r + 8][c + 4];
            }
            uint32_t bfr[4][2];
#pragma unroll
            for (int nf = 0; nf < 4; nf++) {
                const int nn = wn * 32 + nf * 8 + g;
                bfr[nf][0] = Bs[buf][c][nn];
                bfr[nf][1] = Bs[buf][c + 4][nn];
            }
#pragma unroll
            for (int mf = 0; mf < 4; mf++)
#pragma unroll
                for (int nf = 0; nf < 4; nf++)
                    mma8(acc[mf][nf], afr[mf], bfr[nf]);
        }
    }

    // Epilogue: + proj_b, inverse window scatter to (t,h,w,c)
#pragma unroll
    for (int mf = 0; mf < 4; mf++) {
        const int row0 = wm * 64 + mf * 16 + (lane >> 2);
#pragma unroll
        for (int nf = 0; nf < 4; nf++) {
            const int col = n0 + wn * 32 + nf * 8 + (lane & 3) * 2;
            const float b0 = pb[col], b1 = pb[col + 1];
            const float* c4 = acc[mf][nf];
#pragma unroll
            for (int half = 0; half < 2; half++) {
                const int grow = rbase + row0 + half * 8;
                const int win = grow >> 6;
                const int p   = grow & 63;
                const int t_idx = win >> 10, wh = (win >> 5) & 31, ww = win & 31;
                const int py = p >> 3, px = p & 7;
                const size_t pix =
                    (((size_t)t_idx * H_DIM + wh * PS + py) * W_DIM + ww * PS + px) * C_DIM;
                float2 v2;
                v2.x = c4[half * 2 + 0] + b0;
                v2.y = c4[half * 2 + 1] + b1;
                *(float2*)(out + pix + col) = v2;
            }
        }
    }
}

// ---------------------------------------------------------------------------
extern "C" void kernel_launch(void* const* d_in, const int* in_sizes, int n_in,
                              void* d_out, int out_size)
{
    const float* vid  = (const float*)d_in[0];
    const float* modu = (const float*)d_in[1];
    const float* wq   = (const float*)d_in[2];
    const float* bq   = (const float*)d_in[3];
    const float* wkv  = (const float*)d_in[4];
    const float* bkv  = (const float*)d_in[5];
    const float* pw   = (const float*)d_in[6];
    const float* pb   = (const float*)d_in[7];
    const float* rpt  = (const float*)d_in[8];
    float* out = (float*)d_out;

    cudaFuncSetAttribute(qkv_tc,  cudaFuncAttributeMaxDynamicSharedMemorySize, SMEM_DYN);
    cudaFuncSetAttribute(proj_tc, cudaFuncAttributeMaxDynamicSharedMemorySize, SMEM_DYN);

    prep_w<<<1024, 256>>>(wq, wkv, pw);
    prep_vid<<<65536, 256>>>(vid);
    prep_modw<<<64, 256>>>(modu, wq, bq, wkv, bkv);
    qkv_tc<<<dim3(6, 2048), 256, SMEM_DYN>>>();
    attn_kernel<<<NWIN * NH, 64>>>(rpt);
    proj_tc<<<dim3(2, 2048), 256, SMEM_DYN>>>(pb, out);
}

// round 8
// speedup vs baseline: 2.6811x; 1.2310x over previous
#include <cuda_runtime.h>
#include <math.h>
#include <stdint.h>

// Problem constants
#define T_DIM   4
#define H_DIM   256
#define W_DIM   256
#define C_DIM   256
#define PS      8
#define NH      8
#define HD      32
#define NTOK    64
#define NWIN    4096
#define NROWS   (NWIN * NTOK)
#define VID_ELEMS ((size_t)T_DIM * H_DIM * W_DIM * C_DIM)

// Scratch (allocation-free rule: __device__ globals)
__device__ uint32_t g_q[(size_t)NWIN * NH * NTOK * HD]; // tf32 [n][h][p][d]
__device__ uint32_t g_k[(size_t)NWIN * NH * NTOK * HD]; // tf32
__device__ uint32_t g_v[(size_t)NWIN * NH * NTOK * HD]; // tf32
__device__ uint32_t g_o[(size_t)NROWS * C_DIM];         // tf32 [n][p][c]
__device__ uint32_t g_vt[VID_ELEMS];                    // tf32 vid
__device__ uint32_t g_wb[256 * 768];                    // tf32 [k][n]: [wq*sc | wkv]
__device__ uint32_t g_pw[256 * 256];                    // tf32 [k][n]: proj_w
__device__ float    g_mw[64 * 768];                     // fp32: modu@W + bias (q scaled)

// ---------------------------------------------------------------------------
__device__ __forceinline__ uint32_t f2tf(float x) {
    uint32_t r;
    asm("cvt.rna.tf32.f32 %0, %1;" : "=r"(r) : "f"(x));
    return r;
}
__device__ __forceinline__ void mma8(float* c, const uint32_t* a, const uint32_t* b) {
    asm volatile(
        "mma.sync.aligned.m16n8k8.row.col.f32.tf32.tf32.f32 "
        "{%0,%1,%2,%3}, {%4,%5,%6,%7}, {%8,%9}, {%0,%1,%2,%3};"
        : "+f"(c[0]), "+f"(c[1]), "+f"(c[2]), "+f"(c[3])
        : "r"(a[0]), "r"(a[1]), "r"(a[2]), "r"(a[3]), "r"(b[0]), "r"(b[1]));
}
__device__ __forceinline__ void cp16(uint32_t s, const void* g) {
    asm volatile("cp.async.ca.shared.global [%0], [%1], 16;" :: "r"(s), "l"(g));
}
#define CP_COMMIT() asm volatile("cp.async.commit_group;" ::: "memory")
#define CP_WAIT(n)  asm volatile("cp.async.wait_group %0;" :: "n"(n) : "memory")

#define APAD 20     // GEMM A k-stride (words)
#define BST  136    // GEMM B n-stride (words)
#define NSTG 3
#define A_STG   (128 * APAD * 4)
#define B_STG   (16 * BST * 4)
#define B_BASE  (NSTG * A_STG)
#define SMEM_DYN (B_BASE + NSTG * B_STG)

// ---------------------------------------------------------------------------
// Prep 1: weights -> tf32 (q-scale folded into wq columns)
// ---------------------------------------------------------------------------
__global__ __launch_bounds__(256) void prep_w(
    const float* __restrict__ wq, const float* __restrict__ wkv,
    const float* __restrict__ pw)
{
    const float sc = 0.1767766952966369f; // 1/sqrt(32)
    int idx = blockIdx.x * 256 + threadIdx.x;
    if (idx < 196608) {
        int k = idx / 768, c = idx % 768;
        float v = (c < 256) ? wq[k * 256 + c] * sc : wkv[k * 512 + (c - 256)];
        g_wb[idx] = f2tf(v);
    } else {
        int j = idx - 196608;
        g_pw[j] = f2tf(pw[j]);
    }
}

__global__ __launch_bounds__(256) void prep_vid(const float* __restrict__ vid)
{
    size_t i = ((size_t)blockIdx.x * 256 + threadIdx.x) * 4;
    float4 v = *(const float4*)(vid + i);
    uint4 o;
    o.x = f2tf(v.x); o.y = f2tf(v.y); o.z = f2tf(v.z); o.w = f2tf(v.w);
    *(uint4*)(g_vt + i) = o;
}

__global__ __launch_bounds__(256) void prep_modw(
    const float* __restrict__ modu,
    const float* __restrict__ wq,  const float* __restrict__ bq,
    const float* __restrict__ wkv, const float* __restrict__ bkv)
{
    __shared__ float m[256];
    const int p = blockIdx.x;
    m[threadIdx.x] = modu[p * 256 + threadIdx.x];
    __syncthreads();
    const float sc = 0.1767766952966369f;
#pragma unroll
    for (int rep = 0; rep < 3; rep++) {
        int c = rep * 256 + threadIdx.x;
        float s = 0.f;
        if (c < 256) {
            for (int k = 0; k < 256; k++) s = fmaf(m[k], wq[k * 256 + c], s);
            s = (s + bq[c]) * sc;
        } else {
            int cc = c - 256;
            for (int k = 0; k < 256; k++) s = fmaf(m[k], wkv[k * 512 + cc], s);
            s += bkv[cc];
        }
        g_mw[p * 768 + c] = s;
    }
}

// ---------------------------------------------------------------------------
// Kernel A (TF32 MMA): X @ [wq|wkv]. Same as R7 except tf32 output.
// grid = (6, 2048).
// ---------------------------------------------------------------------------
__global__ __launch_bounds__(256, 2) void qkv_tc()
{
    extern __shared__ uint32_t smem[];
    uint32_t (*As)[128][APAD] = (uint32_t(*)[128][APAD])smem;
    uint32_t (*Bs)[16][BST]   = (uint32_t(*)[16][BST])(smem + B_BASE / 4);
    const uint32_t su = (uint32_t)__cvta_generic_to_shared(smem);

    const int tid  = threadIdx.x;
    const int lane = tid & 31;
    const int warp = tid >> 5;
    const int wm   = warp >> 2;
    const int wn   = warp & 3;
    const int n2   = blockIdx.y * 2;
    const int n0   = blockIdx.x * 128;

    const int arow = tid >> 1;
    const int ac0  = (tid & 1) * 8;
    const int wgt  = n2 + (arow >> 6);
    const int p    = arow & 63;
    const int t_idx = wgt >> 10, wh = (wgt >> 5) & 31, ww = wgt & 31;
    const int py = p >> 3, px = p & 7;
    const uint32_t* aptr = g_vt +
        (((size_t)t_idx * H_DIM + wh * PS + py) * W_DIM + ww * PS + px) * C_DIM + ac0;
    const uint32_t ad = su + (uint32_t)(arow * APAD + ac0) * 4;

    const int br = tid >> 4;
    const int bc = (tid & 15) * 8;
    const uint32_t* bptr = g_wb + (size_t)br * 768 + n0 + bc;
    const uint32_t bd = su + B_BASE + (uint32_t)(br * BST + bc) * 4;

    float acc[4][4][4];
#pragma unroll
    for (int i = 0; i < 4; i++)
#pragma unroll
        for (int j = 0; j < 4; j++)
#pragma unroll
            for (int e = 0; e < 4; e++) acc[i][j][e] = 0.f;

#pragma unroll
    for (int s = 0; s < 2; s++) {
        const int k0 = s * 16;
        cp16(ad + s * A_STG, aptr + k0);  cp16(ad + s * A_STG + 16, aptr + k0 + 4);
        cp16(bd + s * B_STG, bptr + (size_t)k0 * 768);
        cp16(bd + s * B_STG + 16, bptr + (size_t)k0 * 768 + 4);
        CP_COMMIT();
    }

#pragma unroll 1
    for (int kt = 0; kt < 16; ++kt) {
        if (kt < 14) CP_WAIT(1); else CP_WAIT(0);
        __syncthreads();
        if (kt + 2 < 16) {
            const int s = (kt + 2) % NSTG;
            const int k0 = (kt + 2) * 16;
            cp16(ad + s * A_STG, aptr + k0);  cp16(ad + s * A_STG + 16, aptr + k0 + 4);
            cp16(bd + s * B_STG, bptr + (size_t)k0 * 768);
            cp16(bd + s * B_STG + 16, bptr + (size_t)k0 * 768 + 4);
            CP_COMMIT();
        }

        const int buf = kt % NSTG;
        const int t = lane & 3, g = lane >> 2;
#pragma unroll
        for (int ks = 0; ks < 2; ks++) {
            const int c = ks * 8 + t;
            uint32_t afr[4][4];
#pragma unroll
            for (int mf = 0; mf < 4; mf++) {
                const int r = wm * 64 + mf * 16 + g;
                afr[mf][0] = As[buf][r][c];
                afr[mf][1] = As[buf][r + 8][c];
                afr[mf][2] = As[buf][r][c + 4];
                afr[mf][3] = As[buf][r + 8][c + 4];
            }
            uint32_t bfr[4][2];
#pragma unroll
            for (int nf = 0; nf < 4; nf++) {
                const int nn = wn * 32 + nf * 8 + g;
                bfr[nf][0] = Bs[buf][c][nn];
                bfr[nf][1] = Bs[buf][c + 4][nn];
            }
#pragma unroll
            for (int mf = 0; mf < 4; mf++)
#pragma unroll
                for (int nf = 0; nf < 4; nf++)
                    mma8(acc[mf][nf], afr[mf], bfr[nf]);
        }
    }

    // Epilogue: + modw, convert tf32, scatter to [n][h][p][d]
    const int seg = n0 >> 8;
    uint32_t* dst = (seg == 0) ? g_q : (seg == 1) ? g_k : g_v;
#pragma unroll
    for (int mf = 0; mf < 4; mf++) {
        const int row0 = wm * 64 + mf * 16 + (lane >> 2);
#pragma unroll
        for (int nf = 0; nf < 4; nf++) {
            const int clg = n0 + wn * 32 + nf * 8 + (lane & 3) * 2;
            const int cc  = clg & 255;
            const int hh  = cc >> 5, d0 = cc & 31;
            const float* c4 = acc[mf][nf];
#pragma unroll
            for (int half = 0; half < 2; half++) {
                const int row = row0 + half * 8;
                const int win = n2 + (row >> 6);
                const int pp  = row & 63;
                const float2 mwv = *(const float2*)(g_mw + pp * 768 + clg);
                uint2 v2;
                v2.x = f2tf(c4[half * 2 + 0] + mwv.x);
                v2.y = f2tf(c4[half * 2 + 1] + mwv.y);
                *(uint2*)(dst + (((size_t)win * NH + hh) * NTOK + pp) * HD + d0) = v2;
            }
        }
    }
}

// ---------------------------------------------------------------------------
// Kernel B (TF32 MMA attention): block = (window, head), 128 thr / 4 warps.
// QK^T -> S+bias -> softmax -> PV. grid = NWIN*NH.
// ---------------------------------------------------------------------------
__global__ __launch_bounds__(128, 4) void attn_tc(const float* __restrict__ rpt)
{
    __shared__ uint32_t Qs[64][36];   // [token][d] tf32
    __shared__ uint32_t Ks[64][36];   // [token][d] tf32
    __shared__ uint32_t Vs[64][40];   // [token][d] tf32
    __shared__ float    Ps[64][68];   // S then P
    __shared__ float    bsb[226];

    const int b = blockIdx.x;
    const int h = b & 7;
    const int n = b >> 3;
    const int tid  = threadIdx.x;
    const int lane = tid & 31;
    const int warp = tid >> 5;
    const size_t base = (size_t)b * (NTOK * HD);

    // Stage Q/K/V via cp.async (16B chunks), bias via LDG
    {
        const uint32_t sq = (uint32_t)__cvta_generic_to_shared(Qs);
        const uint32_t sk = (uint32_t)__cvta_generic_to_shared(Ks);
        const uint32_t sv = (uint32_t)__cvta_generic_to_shared(Vs);
#pragma unroll
        for (int it = 0; it < 4; it++) {
            const int idx = tid + it * 128;
            const int p  = idx >> 3;
            const int q4 = (idx & 7) * 4;
            cp16(sq + (uint32_t)(p * 36 + q4) * 4, g_q + base + p * 32 + q4);
            cp16(sk + (uint32_t)(p * 36 + q4) * 4, g_k + base + p * 32 + q4);
            cp16(sv + (uint32_t)(p * 40 + q4) * 4, g_v + base + p * 32 + q4);
        }
        CP_COMMIT();
        for (int i = tid; i < 225; i += 128) bsb[i] = rpt[(size_t)i * NH + h];
        CP_WAIT(0);
    }
    __syncthreads();

    const int t = lane & 3, g = lane >> 2;

    // ---- QK^T: warp computes S[:, warp*16 .. +15] ----
    float acc[4][2][4];
#pragma unroll
    for (int i = 0; i < 4; i++)
#pragma unroll
        for (int j = 0; j < 2; j++)
#pragma unroll
            for (int e = 0; e < 4; e++) acc[i][j][e] = 0.f;

#pragma unroll
    for (int kt = 0; kt < 4; kt++) {
        const int c = kt * 8 + t;
        uint32_t af[4][4];
#pragma unroll
        for (int mt = 0; mt < 4; mt++) {
            const int r = mt * 16 + g;
            af[mt][0] = Qs[r][c];     af[mt][1] = Qs[r + 8][c];
            af[mt][2] = Qs[r][c + 4]; af[mt][3] = Qs[r + 8][c + 4];
        }
        uint32_t bf[2][2];
#pragma unroll
        for (int nt = 0; nt < 2; nt++) {
            const int nn = warp * 16 + nt * 8 + g;
            bf[nt][0] = Ks[nn][c];
            bf[nt][1] = Ks[nn][c + 4];
        }
#pragma unroll
        for (int mt = 0; mt < 4; mt++)
#pragma unroll
            for (int nt = 0; nt < 2; nt++)
                mma8(acc[mt][nt], af[mt], bf[nt]);
    }

    // Store S + rel-pos bias (fp32) to Ps
#pragma unroll
    for (int mt = 0; mt < 4; mt++) {
#pragma unroll
        for (int nt = 0; nt < 2; nt++) {
            const int col = warp * 16 + nt * 8 + 2 * t;
            const int ky = col >> 3, kx = col & 7;
            const int ky1 = (col + 1) >> 3, kx1 = (col + 1) & 7;
            const float* c4 = acc[mt][nt];
#pragma unroll
            for (int half = 0; half < 2; half++) {
                const int r = mt * 16 + g + half * 8;
                const int qy = r >> 3, qx = r & 7;
                Ps[r][col]     = c4[half * 2 + 0] + bsb[(qy - ky  + 7) * 15 + (qx - kx  + 7)];
                Ps[r][col + 1] = c4[half * 2 + 1] + bsb[(qy - ky1 + 7) * 15 + (qx - kx1 + 7)];
            }
        }
    }
    __syncthreads();

    // ---- Softmax: thread handles row tid>>1, half (tid&1)*32 ----
    {
        const int r  = tid >> 1;
        const int h0 = (tid & 1) * 32;
        float s[32];
        float mx = -1e30f;
#pragma unroll
        for (int j = 0; j < 32; j++) { s[j] = Ps[r][h0 + j]; mx = fmaxf(mx, s[j]); }
        mx = fmaxf(mx, __shfl_xor_sync(0xffffffffu, mx, 1));
        float sum = 0.f;
#pragma unroll
        for (int j = 0; j < 32; j++) { s[j] = __expf(s[j] - mx); sum += s[j]; }
        sum += __shfl_xor_sync(0xffffffffu, sum, 1);
        const float inv = 1.0f / sum;
#pragma unroll
        for (int j = 0; j < 32; j++)
            Ps[r][h0 + j] = __uint_as_float(f2tf(s[j] * inv));
    }
    __syncthreads();

    // ---- PV: warp computes O rows warp*16 .. +15, all 32 dims ----
    float acc2[4][4];
#pragma unroll
    for (int i = 0; i < 4; i++)
#pragma unroll
        for (int e = 0; e < 4; e++) acc2[i][e] = 0.f;

#pragma unroll
    for (int kt = 0; kt < 8; kt++) {
        const int c = kt * 8 + t;
        const int r = warp * 16 + g;
        uint32_t af[4];
        af[0] = __float_as_uint(Ps[r][c]);
        af[1] = __float_as_uint(Ps[r + 8][c]);
        af[2] = __float_as_uint(Ps[r][c + 4]);
        af[3] = __float_as_uint(Ps[r + 8][c + 4]);
        uint32_t bf[4][2];
#pragma unroll
        for (int nt = 0; nt < 4; nt++) {
            const int nn = nt * 8 + g;
            bf[nt][0] = Vs[c][nn];
            bf[nt][1] = Vs[c + 4][nn];
        }
#pragma unroll
        for (int nt = 0; nt < 4; nt++)
            mma8(acc2[nt], af, bf[nt]);
    }

    // Write O (tf32) to g_o[n][p][h*32 + d]
#pragma unroll
    for (int nt = 0; nt < 4; nt++) {
        const int col = nt * 8 + 2 * t;
#pragma unroll
        for (int half = 0; half < 2; half++) {
            const int p = warp * 16 + g + half * 8;
            uint2 v2;
            v2.x = f2tf(acc2[nt][half * 2 + 0]);
            v2.y = f2tf(acc2[nt][half * 2 + 1]);
            *(uint2*)(g_o + ((size_t)n * NTOK + p) * C_DIM + h * HD + col) = v2;
        }
    }
}

// ---------------------------------------------------------------------------
// Kernel C (TF32 MMA): proj GEMM + inverse window scatter. grid = (2, 2048).
// ---------------------------------------------------------------------------
__global__ __launch_bounds__(256, 2) void proj_tc(
    const float* __restrict__ pb, float* __restrict__ out)
{
    extern __shared__ uint32_t smem[];
    uint32_t (*As)[128][APAD] = (uint32_t(*)[128][APAD])smem;
    uint32_t (*Bs)[16][BST]   = (uint32_t(*)[16][BST])(smem + B_BASE / 4);

    const int tid  = threadIdx.x;
    const int lane = tid & 31;
    const int warp = tid >> 5;
    const int wm   = warp >> 2;
    const int wn   = warp & 3;
    const int rbase = blockIdx.y * 128;
    const int n0    = blockIdx.x * 128;
    const uint32_t su = (uint32_t)__cvta_generic_to_shared(smem);

    const int arow = tid >> 1;
    const int ac0  = (tid & 1) * 8;
    const uint32_t* aptr = g_o + (size_t)(rbase + arow) * C_DIM + ac0;
    const uint32_t ad = su + (uint32_t)(arow * APAD + ac0) * 4;

    const int br = tid >> 4;
    const int bc = (tid & 15) * 8;
    const uint32_t* bptr = g_pw + (size_t)br * 256 + n0 + bc;
    const uint32_t bd = su + B_BASE + (uint32_t)(br * BST + bc) * 4;

    float acc[4][4][4];
#pragma unroll
    for (int i = 0; i < 4; i++)
#pragma unroll
        for (int j = 0; j < 4; j++)
#pragma unroll
            for (int e = 0; e < 4; e++) acc[i][j][e] = 0.f;

#pragma unroll
    for (int s = 0; s < 2; s++) {
        const int k0 = s * 16;
        cp16(ad + s * A_STG, aptr + k0);  cp16(ad + s * A_STG + 16, aptr + k0 + 4);
        cp16(bd + s * B_STG, bptr + (size_t)k0 * 256);
        cp16(bd + s * B_STG + 16, bptr + (size_t)k0 * 256 + 4);
        CP_COMMIT();
    }

#pragma unroll 1
    for (int kt = 0; kt < 16; ++kt) {
        if (kt < 14) CP_WAIT(1); else CP_WAIT(0);
        __syncthreads();
        if (kt + 2 < 16) {
            const int s = (kt + 2) % NSTG;
            const int k0 = (kt + 2) * 16;
            cp16(ad + s * A_STG, aptr + k0);  cp16(ad + s * A_STG + 16, aptr + k0 + 4);
            cp16(bd + s * B_STG, bptr + (size_t)k0 * 256);
            cp16(bd + s * B_STG + 16, bptr + (size_t)k0 * 256 + 4);
            CP_COMMIT();
        }

        const int buf = kt % NSTG;
        const int t = lane & 3, g = lane >> 2;
#pragma unroll
        for (int ks = 0; ks < 2; ks++) {
            const int c = ks * 8 + t;
            uint32_t afr[4][4];
#pragma unroll
            for (int mf = 0; mf < 4; mf++) {
                const int r = wm * 64 + mf * 16 + g;
                afr[mf][0] = As[buf][r][c];
                afr[mf][1] = As[buf][r + 8][c];
                afr[mf][2] = As[buf][r][c + 4];
                afr[mf][3] = As[buf][r + 8][c + 4];
            }
            uint32_t bfr[4][2];
#pragma unroll
            for (int nf = 0; nf < 4; nf++) {
                const int nn = wn * 32 + nf * 8 + g;
                bfr[nf][0] = Bs[buf][c][nn];
                bfr[nf][1] = Bs[buf][c + 4][nn];
            }
#pragma unroll
            for (int mf = 0; mf < 4; mf++)
#pragma unroll
                for (int nf = 0; nf < 4; nf++)
                    mma8(acc[mf][nf], afr[mf], bfr[nf]);
        }
    }

#pragma unroll
    for (int mf = 0; mf < 4; mf++) {
        const int row0 = wm * 64 + mf * 16 + (lane >> 2);
#pragma unroll
        for (int nf = 0; nf < 4; nf++) {
            const int col = n0 + wn * 32 + nf * 8 + (lane & 3) * 2;
            const float b0 = pb[col], b1 = pb[col + 1];
            const float* c4 = acc[mf][nf];
#pragma unroll
            for (int half = 0; half < 2; half++) {
                const int grow = rbase + row0 + half * 8;
                const int win = grow >> 6;
                const int p   = grow & 63;
                const int t_idx = win >> 10, wh = (win >> 5) & 31, ww = win & 31;
                const int py = p >> 3, px = p & 7;
                const size_t pix =
                    (((size_t)t_idx * H_DIM + wh * PS + py) * W_DIM + ww * PS + px) * C_DIM;
                float2 v2;
                v2.x = c4[half * 2 + 0] + b0;
                v2.y = c4[half * 2 + 1] + b1;
                *(float2*)(out + pix + col) = v2;
            }
        }
    }
}

// ---------------------------------------------------------------------------
extern "C" void kernel_launch(void* const* d_in, const int* in_sizes, int n_in,
                              void* d_out, int out_size)
{
    const float* vid  = (const float*)d_in[0];
    const float* modu = (const float*)d_in[1];
    const float* wq   = (const float*)d_in[2];
    const float* bq   = (const float*)d_in[3];
    const float* wkv  = (const float*)d_in[4];
    const float* bkv  = (const float*)d_in[5];
    const float* pw   = (const float*)d_in[6];
    const float* pb   = (const float*)d_in[7];
    const float* rpt  = (const float*)d_in[8];
    float* out = (float*)d_out;

    cudaFuncSetAttribute(qkv_tc,  cudaFuncAttributeMaxDynamicSharedMemorySize, SMEM_DYN);
    cudaFuncSetAttribute(proj_tc, cudaFuncAttributeMaxDynamicSharedMemorySize, SMEM_DYN);

    prep_w<<<1024, 256>>>(wq, wkv, pw);
    prep_vid<<<65536, 256>>>(vid);
    prep_modw<<<64, 256>>>(modu, wq, bq, wkv, bkv);
    qkv_tc<<<dim3(6, 2048), 256, SMEM_DYN>>>();
    attn_tc<<<NWIN * NH, 128>>>(rpt);
    proj_tc<<<dim3(2, 2048), 256, SMEM_DYN>>>(pb, out);
}

// round 9
// speedup vs baseline: 2.9935x; 1.1165x over previous
#include <cuda_runtime.h>
#include <math.h>
#include <stdint.h>

// Problem constants
#define T_DIM   4
#define H_DIM   256
#define W_DIM   256
#define C_DIM   256
#define PS      8
#define NH      8
#define HD      32
#define NTOK    64
#define NWIN    4096
#define NROWS   (NWIN * NTOK)
#define VID_ELEMS ((size_t)T_DIM * H_DIM * W_DIM * C_DIM)

// Scratch (allocation-free rule: __device__ globals)
__device__ uint32_t g_q[(size_t)NWIN * NH * NTOK * HD]; // tf32 [n][h][p][d]
__device__ uint32_t g_k[(size_t)NWIN * NH * NTOK * HD]; // tf32
__device__ uint32_t g_v[(size_t)NWIN * NH * NTOK * HD]; // tf32
__device__ uint32_t g_o[(size_t)NROWS * C_DIM];         // tf32 [n][p][c]
__device__ uint32_t g_vt[VID_ELEMS];                    // tf32 vid
__device__ uint32_t g_wbt[768 * 256];                   // tf32 [n][k]: [wq*sc|wkv]^T
__device__ uint32_t g_pwt[256 * 256];                   // tf32 [n][k]: proj_w^T
__device__ float    g_mw[64 * 768];                     // fp32: modu@W + bias (q scaled)

// ---------------------------------------------------------------------------
__device__ __forceinline__ uint32_t f2tf(float x) {
    uint32_t r;
    asm("cvt.rna.tf32.f32 %0, %1;" : "=r"(r) : "f"(x));
    return r;
}
__device__ __forceinline__ void mma8(float* c, const uint32_t* a, const uint32_t* b) {
    asm volatile(
        "mma.sync.aligned.m16n8k8.row.col.f32.tf32.tf32.f32 "
        "{%0,%1,%2,%3}, {%4,%5,%6,%7}, {%8,%9}, {%0,%1,%2,%3};"
        : "+f"(c[0]), "+f"(c[1]), "+f"(c[2]), "+f"(c[3])
        : "r"(a[0]), "r"(a[1]), "r"(a[2]), "r"(a[3]), "r"(b[0]), "r"(b[1]));
}
__device__ __forceinline__ void ldsm4(uint32_t& r0, uint32_t& r1, uint32_t& r2,
                                      uint32_t& r3, uint32_t addr) {
    asm volatile("ldmatrix.sync.aligned.m8n8.x4.shared.b16 {%0,%1,%2,%3}, [%4];"
        : "=r"(r0), "=r"(r1), "=r"(r2), "=r"(r3) : "r"(addr));
}
__device__ __forceinline__ void cp16(uint32_t s, const void* g) {
    asm volatile("cp.async.ca.shared.global [%0], [%1], 16;" :: "r"(s), "l"(g));
}
#define CP_COMMIT() asm volatile("cp.async.commit_group;" ::: "memory")
#define CP_WAIT(n)  asm volatile("cp.async.wait_group %0;" :: "n"(n) : "memory")

#define STR 20                      // row stride (words): LDSM rows conflict-free
#define NSTG 3
#define TILE_STG (128 * STR * 4)    // 10240 B per operand stage
#define B_BASE   (NSTG * TILE_STG)  // 30720
#define SMEM_DYN (2 * NSTG * TILE_STG)  // 61440

// ---------------------------------------------------------------------------
// Prep 1: weights -> tf32, TRANSPOSED to [n][k] (q-scale folded)
// ---------------------------------------------------------------------------
__global__ __launch_bounds__(256) void prep_w(
    const float* __restrict__ wq, const float* __restrict__ wkv,
    const float* __restrict__ pw)
{
    const float sc = 0.1767766952966369f; // 1/sqrt(32)
    int idx = blockIdx.x * 256 + threadIdx.x;
    if (idx < 196608) {
        int n = idx >> 8, k = idx & 255;
        float v = (n < 256) ? wq[k * 256 + n] * sc : wkv[k * 512 + (n - 256)];
        g_wbt[idx] = f2tf(v);
    } else {
        int j = idx - 196608;
        int n = j >> 8, k = j & 255;
        g_pwt[j] = f2tf(pw[k * 256 + n]);
    }
}

__global__ __launch_bounds__(256) void prep_vid(const float* __restrict__ vid)
{
    size_t i = ((size_t)blockIdx.x * 256 + threadIdx.x) * 4;
    float4 v = *(const float4*)(vid + i);
    uint4 o;
    o.x = f2tf(v.x); o.y = f2tf(v.y); o.z = f2tf(v.z); o.w = f2tf(v.w);
    *(uint4*)(g_vt + i) = o;
}

__global__ __launch_bounds__(256) void prep_modw(
    const float* __restrict__ modu,
    const float* __restrict__ wq,  const float* __restrict__ bq,
    const float* __restrict__ wkv, const float* __restrict__ bkv)
{
    __shared__ float m[256];
    const int p = blockIdx.x;
    m[threadIdx.x] = modu[p * 256 + threadIdx.x];
    __syncthreads();
    const float sc = 0.1767766952966369f;
#pragma unroll
    for (int rep = 0; rep < 3; rep++) {
        int c = rep * 256 + threadIdx.x;
        float s = 0.f;
        if (c < 256) {
            for (int k = 0; k < 256; k++) s = fmaf(m[k], wq[k * 256 + c], s);
            s = (s + bq[c]) * sc;
        } else {
            int cc = c - 256;
            for (int k = 0; k < 256; k++) s = fmaf(m[k], wkv[k * 512 + cc], s);
            s += bkv[cc];
        }
        g_mw[p * 768 + c] = s;
    }
}

// ---------------------------------------------------------------------------
// Kernel A (TF32 MMA + ldmatrix): X @ [wq|wkv]. BM=128, BN=128, BK=16,
// 3-stage cp.async. 8 warps (2m x 4n), warp tile 64x32. grid = (6, 2048).
// ---------------------------------------------------------------------------
__global__ __launch_bounds__(256, 2) void qkv_tc()
{
    extern __shared__ uint32_t smem[];
    const uint32_t su = (uint32_t)__cvta_generic_to_shared(smem);

    const int tid  = threadIdx.x;
    const int lane = tid & 31;
    const int warp = tid >> 5;
    const int wm   = warp >> 2;
    const int wn   = warp & 3;
    const int n2   = blockIdx.y * 2;
    const int n0   = blockIdx.x * 128;

    // cp.async mapping: thread covers rows r0 and r0+64, 16B chunk kc
    const int r0 = tid >> 2;
    const int kc = tid & 3;
    // A row pointers (window gather)
    const int w0 = n2 + (r0 >> 6);           // r0<64 -> n2
    const int p0 = r0 & 63;
    const int p1 = p0;                        // row r0+64 -> window n2+1, same token idx
    const int ti0 = w0 >> 10, wh0 = (w0 >> 5) & 31, ww0 = w0 & 31;
    const int w1 = w0 + 1;
    const int ti1 = w1 >> 10, wh1 = (w1 >> 5) & 31, ww1 = w1 & 31;
    const uint32_t* ap0 = g_vt +
        (((size_t)ti0 * H_DIM + wh0 * PS + (p0 >> 3)) * W_DIM + ww0 * PS + (p0 & 7)) * C_DIM + kc * 4;
    const uint32_t* ap1 = g_vt +
        (((size_t)ti1 * H_DIM + wh1 * PS + (p1 >> 3)) * W_DIM + ww1 * PS + (p1 & 7)) * C_DIM + kc * 4;
    const uint32_t ao0 = (uint32_t)(r0 * STR + kc * 4) * 4;
    const uint32_t ao1 = (uint32_t)((r0 + 64) * STR + kc * 4) * 4;
    // B row pointers
    const uint32_t* bp0 = g_wbt + (size_t)(n0 + r0) * 256 + kc * 4;
    const uint32_t* bp1 = g_wbt + (size_t)(n0 + r0 + 64) * 256 + kc * 4;

    // ldmatrix per-thread offsets
    const uint32_t a_off = (uint32_t)((wm * 64 + (lane & 7) + ((lane >> 3) & 1) * 8) * STR
                                     + ((lane >> 4) & 1) * 4) * 4;
    const uint32_t b_off = (uint32_t)((wn * 32 + (lane & 7) + ((lane >> 4) & 1) * 8) * STR
                                     + ((lane >> 3) & 1) * 4) * 4;

    float acc[4][4][4];
#pragma unroll
    for (int i = 0; i < 4; i++)
#pragma unroll
        for (int j = 0; j < 4; j++)
#pragma unroll
            for (int e = 0; e < 4; e++) acc[i][j][e] = 0.f;

    // Prologue: stages 0,1 (ktiles 0,1)
#pragma unroll
    for (int s = 0; s < 2; s++) {
        const int k0 = s * 16;
        cp16(su + s * TILE_STG + ao0, ap0 + k0);
        cp16(su + s * TILE_STG + ao1, ap1 + k0);
        cp16(su + B_BASE + s * TILE_STG + ao0, bp0 + k0);
        cp16(su + B_BASE + s * TILE_STG + ao1, bp1 + k0);
        CP_COMMIT();
    }

#pragma unroll 1
    for (int kt = 0; kt < 16; ++kt) {
        if (kt < 14) CP_WAIT(1); else CP_WAIT(0);
        __syncthreads();
        if (kt + 2 < 16) {
            const int s = (kt + 2) % NSTG;
            const int k0 = (kt + 2) * 16;
            cp16(su + s * TILE_STG + ao0, ap0 + k0);
            cp16(su + s * TILE_STG + ao1, ap1 + k0);
            cp16(su + B_BASE + s * TILE_STG + ao0, bp0 + k0);
            cp16(su + B_BASE + s * TILE_STG + ao1, bp1 + k0);
            CP_COMMIT();
        }

        const int buf = kt % NSTG;
        const uint32_t abase = su + buf * TILE_STG + a_off;
        const uint32_t bbase = su + B_BASE + buf * TILE_STG + b_off;
#pragma unroll
        for (int ks = 0; ks < 2; ks++) {
            uint32_t afr[4][4];
#pragma unroll
            for (int mf = 0; mf < 4; mf++)
                ldsm4(afr[mf][0], afr[mf][1], afr[mf][2], afr[mf][3],
                      abase + (uint32_t)(mf * 16 * STR + ks * 8) * 4);
            uint32_t bfr[4][2];
            ldsm4(bfr[0][0], bfr[0][1], bfr[1][0], bfr[1][1],
                  bbase + (uint32_t)(ks * 8) * 4);
            ldsm4(bfr[2][0], bfr[2][1], bfr[3][0], bfr[3][1],
                  bbase + (uint32_t)(16 * STR + ks * 8) * 4);
#pragma unroll
            for (int mf = 0; mf < 4; mf++)
#pragma unroll
                for (int nf = 0; nf < 4; nf++)
                    mma8(acc[mf][nf], afr[mf], bfr[nf]);
        }
    }

    // Epilogue: + modw, convert tf32, scatter to [n][h][p][d]
    const int seg = n0 >> 8;
    uint32_t* dst = (seg == 0) ? g_q : (seg == 1) ? g_k : g_v;
#pragma unroll
    for (int mf = 0; mf < 4; mf++) {
        const int row0 = wm * 64 + mf * 16 + (lane >> 2);
#pragma unroll
        for (int nf = 0; nf < 4; nf++) {
            const int clg = n0 + wn * 32 + nf * 8 + (lane & 3) * 2;
            const int cc  = clg & 255;
            const int hh  = cc >> 5, d0 = cc & 31;
            const float* c4 = acc[mf][nf];
#pragma unroll
            for (int half = 0; half < 2; half++) {
                const int row = row0 + half * 8;
                const int win = n2 + (row >> 6);
                const int pp  = row & 63;
                const float2 mwv = *(const float2*)(g_mw + pp * 768 + clg);
                uint2 v2;
                v2.x = f2tf(c4[half * 2 + 0] + mwv.x);
                v2.y = f2tf(c4[half * 2 + 1] + mwv.y);
                *(uint2*)(dst + (((size_t)win * NH + hh) * NTOK + pp) * HD + d0) = v2;
            }
        }
    }
}

// ---------------------------------------------------------------------------
// Kernel B (TF32 MMA attention): block = (window, head), 128 thr / 4 warps.
// ---------------------------------------------------------------------------
__global__ __launch_bounds__(128, 4) void attn_tc(const float* __restrict__ rpt)
{
    __shared__ uint32_t Qs[64][36];
    __shared__ uint32_t Ks[64][36];
    __shared__ uint32_t Vs[64][40];
    __shared__ float    Ps[64][68];
    __shared__ float    bsb[226];

    const int b = blockIdx.x;
    const int h = b & 7;
    const int n = b >> 3;
    const int tid  = threadIdx.x;
    const int lane = tid & 31;
    const int warp = tid >> 5;
    const size_t base = (size_t)b * (NTOK * HD);

    {
        const uint32_t sq = (uint32_t)__cvta_generic_to_shared(Qs);
        const uint32_t sk = (uint32_t)__cvta_generic_to_shared(Ks);
        const uint32_t sv = (uint32_t)__cvta_generic_to_shared(Vs);
#pragma unroll
        for (int it = 0; it < 4; it++) {
            const int idx = tid + it * 128;
            const int p  = idx >> 3;
            const int q4 = (idx & 7) * 4;
            cp16(sq + (uint32_t)(p * 36 + q4) * 4, g_q + base + p * 32 + q4);
            cp16(sk + (uint32_t)(p * 36 + q4) * 4, g_k + base + p * 32 + q4);
            cp16(sv + (uint32_t)(p * 40 + q4) * 4, g_v + base + p * 32 + q4);
        }
        CP_COMMIT();
        for (int i = tid; i < 225; i += 128) bsb[i] = rpt[(size_t)i * NH + h];
        CP_WAIT(0);
    }
    __syncthreads();

    const int t = lane & 3, g = lane >> 2;

    float acc[4][2][4];
#pragma unroll
    for (int i = 0; i < 4; i++)
#pragma unroll
        for (int j = 0; j < 2; j++)
#pragma unroll
            for (int e = 0; e < 4; e++) acc[i][j][e] = 0.f;

#pragma unroll
    for (int kt = 0; kt < 4; kt++) {
        const int c = kt * 8 + t;
        uint32_t af[4][4];
#pragma unroll
        for (int mt = 0; mt < 4; mt++) {
            const int r = mt * 16 + g;
            af[mt][0] = Qs[r][c];     af[mt][1] = Qs[r + 8][c];
            af[mt][2] = Qs[r][c + 4]; af[mt][3] = Qs[r + 8][c + 4];
        }
        uint32_t bf[2][2];
#pragma unroll
        for (int nt = 0; nt < 2; nt++) {
            const int nn = warp * 16 + nt * 8 + g;
            bf[nt][0] = Ks[nn][c];
            bf[nt][1] = Ks[nn][c + 4];
        }
#pragma unroll
        for (int mt = 0; mt < 4; mt++)
#pragma unroll
            for (int nt = 0; nt < 2; nt++)
                mma8(acc[mt][nt], af[mt], bf[nt]);
    }

#pragma unroll
    for (int mt = 0; mt < 4; mt++) {
#pragma unroll
        for (int nt = 0; nt < 2; nt++) {
            const int col = warp * 16 + nt * 8 + 2 * t;
            const int ky = col >> 3, kx = col & 7;
            const int ky1 = (col + 1) >> 3, kx1 = (col + 1) & 7;
            const float* c4 = acc[mt][nt];
#pragma unroll
            for (int half = 0; half < 2; half++) {
                const int r = mt * 16 + g + half * 8;
                const int qy = r >> 3, qx = r & 7;
                Ps[r][col]     = c4[half * 2 + 0] + bsb[(qy - ky  + 7) * 15 + (qx - kx  + 7)];
                Ps[r][col + 1] = c4[half * 2 + 1] + bsb[(qy - ky1 + 7) * 15 + (qx - kx1 + 7)];
            }
        }
    }
    __syncthreads();

    {
        const int r  = tid >> 1;
        const int h0 = (tid & 1) * 32;
        float s[32];
        float mx = -1e30f;
#pragma unroll
        for (int j = 0; j < 32; j++) { s[j] = Ps[r][h0 + j]; mx = fmaxf(mx, s[j]); }
        mx = fmaxf(mx, __shfl_xor_sync(0xffffffffu, mx, 1));
        float sum = 0.f;
#pragma unroll
        for (int j = 0; j < 32; j++) { s[j] = __expf(s[j] - mx); sum += s[j]; }
        sum += __shfl_xor_sync(0xffffffffu, sum, 1);
        const float inv = 1.0f / sum;
#pragma unroll
        for (int j = 0; j < 32; j++)
            Ps[r][h0 + j] = __uint_as_float(f2tf(s[j] * inv));
    }
    __syncthreads();

    float acc2[4][4];
#pragma unroll
    for (int i = 0; i < 4; i++)
#pragma unroll
        for (int e = 0; e < 4; e++) acc2[i][e] = 0.f;

#pragma unroll
    for (int kt = 0; kt < 8; kt++) {
        const int c = kt * 8 + t;
        const int r = warp * 16 + g;
        uint32_t af[4];
        af[0] = __float_as_uint(Ps[r][c]);
        af[1] = __float_as_uint(Ps[r + 8][c]);
        af[2] = __float_as_uint(Ps[r][c + 4]);
        af[3] = __float_as_uint(Ps[r + 8][c + 4]);
        uint32_t bf[4][2];
#pragma unroll
        for (int nt = 0; nt < 4; nt++) {
            const int nn = nt * 8 + g;
            bf[nt][0] = Vs[c][nn];
            bf[nt][1] = Vs[c + 4][nn];
        }
#pragma unroll
        for (int nt = 0; nt < 4; nt++)
            mma8(acc2[nt], af, bf[nt]);
    }

#pragma unroll
    for (int nt = 0; nt < 4; nt++) {
        const int col = nt * 8 + 2 * t;
#pragma unroll
        for (int half = 0; half < 2; half++) {
            const int p = warp * 16 + g + half * 8;
            uint2 v2;
            v2.x = f2tf(acc2[nt][half * 2 + 0]);
            v2.y = f2tf(acc2[nt][half * 2 + 1]);
            *(uint2*)(g_o + ((size_t)n * NTOK + p) * C_DIM + h * HD + col) = v2;
        }
    }
}

// ---------------------------------------------------------------------------
// Kernel C (TF32 MMA + ldmatrix): proj GEMM + inverse window scatter.
// grid = (2, 2048).
// ---------------------------------------------------------------------------
__global__ __launch_bounds__(256, 2) void proj_tc(
    const float* __restrict__ pb, float* __restrict__ out)
{
    extern __shared__ uint32_t smem[];
    const uint32_t su = (uint32_t)__cvta_generic_to_shared(smem);

    const int tid  = threadIdx.x;
    const int lane = tid & 31;
    const int warp = tid >> 5;
    const int wm   = warp >> 2;
    const int wn   = warp & 3;
    const int rbase = blockIdx.y * 128;
    const int n0    = blockIdx.x * 128;

    const int r0 = tid >> 2;
    const int kc = tid & 3;
    const uint32_t* ap0 = g_o + (size_t)(rbase + r0) * 256 + kc * 4;
    const uint32_t* ap1 = g_o + (size_t)(rbase + r0 + 64) * 256 + kc * 4;
    const uint32_t ao0 = (uint32_t)(r0 * STR + kc * 4) * 4;
    const uint32_t ao1 = (uint32_t)((r0 + 64) * STR + kc * 4) * 4;
    const uint32_t* bp0 = g_pwt + (size_t)(n0 + r0) * 256 + kc * 4;
    const uint32_t* bp1 = g_pwt + (size_t)(n0 + r0 + 64) * 256 + kc * 4;

    const uint32_t a_off = (uint32_t)((wm * 64 + (lane & 7) + ((lane >> 3) & 1) * 8) * STR
                                     + ((lane >> 4) & 1) * 4) * 4;
    const uint32_t b_off = (uint32_t)((wn * 32 + (lane & 7) + ((lane >> 4) & 1) * 8) * STR
                                     + ((lane >> 3) & 1) * 4) * 4;

    float acc[4][4][4];
#pragma unroll
    for (int i = 0; i < 4; i++)
#pragma unroll
        for (int j = 0; j < 4; j++)
#pragma unroll
            for (int e = 0; e < 4; e++) acc[i][j][e] = 0.f;

#pragma unroll
    for (int s = 0; s < 2; s++) {
        const int k0 = s * 16;
        cp16(su + s * TILE_STG + ao0, ap0 + k0);
        cp16(su + s * TILE_STG + ao1, ap1 + k0);
        cp16(su + B_BASE + s * TILE_STG + ao0, bp0 + k0);
        cp16(su + B_BASE + s * TILE_STG + ao1, bp1 + k0);
        CP_COMMIT();
    }

#pragma unroll 1
    for (int kt = 0; kt < 16; ++kt) {
        if (kt < 14) CP_WAIT(1); else CP_WAIT(0);
        __syncthreads();
        if (kt + 2 < 16) {
            const int s = (kt + 2) % NSTG;
            const int k0 = (kt + 2) * 16;
            cp16(su + s * TILE_STG + ao0, ap0 + k0);
            cp16(su + s * TILE_STG + ao1, ap1 + k0);
            cp16(su + B_BASE + s * TILE_STG + ao0, bp0 + k0);
            cp16(su + B_BASE + s * TILE_STG + ao1, bp1 + k0);
            CP_COMMIT();
        }

        const int buf = kt % NSTG;
        const uint32_t abase = su + buf * TILE_STG + a_off;
        const uint32_t bbase = su + B_BASE + buf * TILE_STG + b_off;
#pragma unroll
        for (int ks = 0; ks < 2; ks++) {
            uint32_t afr[4][4];
#pragma unroll
            for (int mf = 0; mf < 4; mf++)
                ldsm4(afr[mf][0], afr[mf][1], afr[mf][2], afr[mf][3],
                      abase + (uint32_t)(mf * 16 * STR + ks * 8) * 4);
            uint32_t bfr[4][2];
            ldsm4(bfr[0][0], bfr[0][1], bfr[1][0], bfr[1][1],
                  bbase + (uint32_t)(ks * 8) * 4);
            ldsm4(bfr[2][0], bfr[2][1], bfr[3][0], bfr[3][1],
                  bbase + (uint32_t)(16 * STR + ks * 8) * 4);
#pragma unroll
            for (int mf = 0; mf < 4; mf++)
#pragma unroll
                for (int nf = 0; nf < 4; nf++)
                    mma8(acc[mf][nf], afr[mf], bfr[nf]);
        }
    }

#pragma unroll
    for (int mf = 0; mf < 4; mf++) {
        const int row0 = wm * 64 + mf * 16 + (lane >> 2);
#pragma unroll
        for (int nf = 0; nf < 4; nf++) {
            const int col = n0 + wn * 32 + nf * 8 + (lane & 3) * 2;
            const float b0 = pb[col], b1 = pb[col + 1];
            const float* c4 = acc[mf][nf];
#pragma unroll
            for (int half = 0; half < 2; half++) {
                const int grow = rbase + row0 + half * 8;
                const int win = grow >> 6;
                const int p   = grow & 63;
                const int t_idx = win >> 10, wh = (win >> 5) & 31, ww = win & 31;
                const int py = p >> 3, px = p & 7;
                const size_t pix =
                    (((size_t)t_idx * H_DIM + wh * PS + py) * W_DIM + ww * PS + px) * C_DIM;
                float2 v2;
                v2.x = c4[half * 2 + 0] + b0;
                v2.y = c4[half * 2 + 1] + b1;
                *(float2*)(out + pix + col) = v2;
            }
        }
    }
}

// ---------------------------------------------------------------------------
extern "C" void kernel_launch(void* const* d_in, const int* in_sizes, int n_in,
                              void* d_out, int out_size)
{
    const float* vid  = (const float*)d_in[0];
    const float* modu = (const float*)d_in[1];
    const float* wq   = (const float*)d_in[2];
    const float* bq   = (const float*)d_in[3];
    const float* wkv  = (const float*)d_in[4];
    const float* bkv  = (const float*)d_in[5];
    const float* pw   = (const float*)d_in[6];
    const float* pb   = (const float*)d_in[7];
    const float* rpt  = (const float*)d_in[8];
    float* out = (float*)d_out;

    cudaFuncSetAttribute(qkv_tc,  cudaFuncAttributeMaxDynamicSharedMemorySize, SMEM_DYN);
    cudaFuncSetAttribute(proj_tc, cudaFuncAttributeMaxDynamicSharedMemorySize, SMEM_DYN);

    prep_w<<<1024, 256>>>(wq, wkv, pw);
    prep_vid<<<65536, 256>>>(vid);
    prep_modw<<<64, 256>>>(modu, wq, bq, wkv, bkv);
    qkv_tc<<<dim3(6, 2048), 256, SMEM_DYN>>>();
    attn_tc<<<NWIN * NH, 128>>>(rpt);
    proj_tc<<<dim3(2, 2048), 256, SMEM_DYN>>>(pb, out);
}

// round 10
// speedup vs baseline: 4.4603x; 1.4900x over previous
#include <cuda_runtime.h>
#include <cuda_fp16.h>
#include <math.h>
#include <stdint.h>

// Problem constants
#define T_DIM   4
#define H_DIM   256
#define W_DIM   256
#define C_DIM   256
#define PS      8
#define NH      8
#define HD      32
#define NTOK    64
#define NWIN    4096
#define NROWS   (NWIN * NTOK)
#define VID_ELEMS ((size_t)T_DIM * H_DIM * W_DIM * C_DIM)

// Scratch (allocation-free rule: __device__ globals)
__device__ __half g_q[(size_t)NWIN * NH * NTOK * HD]; // [n][h][p][d]
__device__ __half g_k[(size_t)NWIN * NH * NTOK * HD];
__device__ __half g_v[(size_t)NWIN * NH * NTOK * HD];
__device__ __half g_o[(size_t)NROWS * C_DIM];         // [n][p][c]
__device__ __half g_vh[VID_ELEMS];                    // fp16 vid
__device__ __half g_wbt[768 * 256];                   // [n][k]: [wq*sc|wkv]^T
__device__ __half g_pwt[256 * 256];                   // [n][k]: proj_w^T
__device__ float  g_mw[64 * 768];                     // fp32: modu@W + bias (q scaled)

// ---------------------------------------------------------------------------
__device__ __forceinline__ void mma_f16(float* c, const uint32_t* a, const uint32_t* b) {
    asm volatile(
        "mma.sync.aligned.m16n8k16.row.col.f32.f16.f16.f32 "
        "{%0,%1,%2,%3}, {%4,%5,%6,%7}, {%8,%9}, {%0,%1,%2,%3};"
        : "+f"(c[0]), "+f"(c[1]), "+f"(c[2]), "+f"(c[3])
        : "r"(a[0]), "r"(a[1]), "r"(a[2]), "r"(a[3]), "r"(b[0]), "r"(b[1]));
}
__device__ __forceinline__ void ldsm4(uint32_t& r0, uint32_t& r1, uint32_t& r2,
                                      uint32_t& r3, uint32_t addr) {
    asm volatile("ldmatrix.sync.aligned.m8n8.x4.shared.b16 {%0,%1,%2,%3}, [%4];"
        : "=r"(r0), "=r"(r1), "=r"(r2), "=r"(r3) : "r"(addr));
}
__device__ __forceinline__ void ldsm4t(uint32_t& r0, uint32_t& r1, uint32_t& r2,
                                       uint32_t& r3, uint32_t addr) {
    asm volatile("ldmatrix.sync.aligned.m8n8.x4.trans.shared.b16 {%0,%1,%2,%3}, [%4];"
        : "=r"(r0), "=r"(r1), "=r"(r2), "=r"(r3) : "r"(addr));
}
__device__ __forceinline__ void cp16(uint32_t s, const void* g) {
    asm volatile("cp.async.ca.shared.global [%0], [%1], 16;" :: "r"(s), "l"(g));
}
#define CP_COMMIT() asm volatile("cp.async.commit_group;" ::: "memory")
#define CP_WAIT(n)  asm volatile("cp.async.wait_group %0;" :: "n"(n) : "memory")

// GEMM smem: rows of 32 halves padded to 40 (80B, s16=5 odd -> LDSM conflict-free)
#define STRB 80                     // row stride bytes
#define NSTG 3
#define TILE_STG (128 * STRB)       // 10240 B per operand stage
#define B_BASE   (NSTG * TILE_STG)
#define SMEM_DYN (2 * NSTG * TILE_STG)  // 61440

// ---------------------------------------------------------------------------
// Prep 1: weights -> fp16 transposed [n][k] (q-scale folded)
// ---------------------------------------------------------------------------
__global__ __launch_bounds__(256) void prep_w(
    const float* __restrict__ wq, const float* __restrict__ wkv,
    const float* __restrict__ pw)
{
    const float sc = 0.1767766952966369f; // 1/sqrt(32)
    int idx = blockIdx.x * 256 + threadIdx.x;
    if (idx < 196608) {
        int n = idx >> 8, k = idx & 255;
        float v = (n < 256) ? wq[k * 256 + n] * sc : wkv[k * 512 + (n - 256)];
        g_wbt[idx] = __float2half_rn(v);
    } else {
        int j = idx - 196608;
        int n = j >> 8, k = j & 255;
        g_pwt[j] = __float2half_rn(pw[k * 256 + n]);
    }
}

// ---------------------------------------------------------------------------
// Prep 2: vid -> fp16 (streaming; 4 elems/thread)
// ---------------------------------------------------------------------------
__global__ __launch_bounds__(256) void prep_vid(const float* __restrict__ vid)
{
    size_t i = ((size_t)blockIdx.x * 256 + threadIdx.x) * 4;
    float4 v = *(const float4*)(vid + i);
    __half2 h0 = __floats2half2_rn(v.x, v.y);
    __half2 h1 = __floats2half2_rn(v.z, v.w);
    uint2 o;
    o.x = *(uint32_t*)&h0;
    o.y = *(uint32_t*)&h1;
    *(uint2*)(g_vh + i) = o;
}

// ---------------------------------------------------------------------------
// Prep 3: modw[p][c] = modu[p]@W + bias (q part scaled). fp32. grid 64 x 256.
// ---------------------------------------------------------------------------
__global__ __launch_bounds__(256) void prep_modw(
    const float* __restrict__ modu,
    const float* __restrict__ wq,  const float* __restrict__ bq,
    const float* __restrict__ wkv, const float* __restrict__ bkv)
{
    __shared__ float m[256];
    const int p = blockIdx.x;
    m[threadIdx.x] = modu[p * 256 + threadIdx.x];
    __syncthreads();
    const float sc = 0.1767766952966369f;
#pragma unroll
    for (int rep = 0; rep < 3; rep++) {
        int c = rep * 256 + threadIdx.x;
        float s = 0.f;
        if (c < 256) {
            for (int k = 0; k < 256; k++) s = fmaf(m[k], wq[k * 256 + c], s);
            s = (s + bq[c]) * sc;
        } else {
            int cc = c - 256;
            for (int k = 0; k < 256; k++) s = fmaf(m[k], wkv[k * 512 + cc], s);
            s += bkv[cc];
        }
        g_mw[p * 768 + c] = s;
    }
}

// ---------------------------------------------------------------------------
// Kernel A (FP16 MMA + ldmatrix): X @ [wq|wkv]. BM=128, BN=128, BK=32 halves,
// 8 iters, 3-stage cp.async. 8 warps (2m x 4n), warp 64x32. grid = (6, 2048).
// ---------------------------------------------------------------------------
__global__ __launch_bounds__(256, 2) void qkv_tc()
{
    extern __shared__ uint32_t smem[];
    const uint32_t su = (uint32_t)__cvta_generic_to_shared(smem);

    const int tid  = threadIdx.x;
    const int lane = tid & 31;
    const int warp = tid >> 5;
    const int wm   = warp >> 2;
    const int wn   = warp & 3;
    const int n2   = blockIdx.y * 2;
    const int n0   = blockIdx.x * 128;

    // cp.async: thread covers rows r0, r0+64; 16B chunk kc (of 4 per 64B row)
    const int r0 = tid >> 2;
    const int kc = tid & 3;
    const int w0 = n2 + (r0 >> 6);
    const int p0 = r0 & 63;
    const int ti0 = w0 >> 10, wh0 = (w0 >> 5) & 31, ww0 = w0 & 31;
    const int w1 = w0 + 1;
    const int ti1 = w1 >> 10, wh1 = (w1 >> 5) & 31, ww1 = w1 & 31;
    const __half* ap0 = g_vh +
        (((size_t)ti0 * H_DIM + wh0 * PS + (p0 >> 3)) * W_DIM + ww0 * PS + (p0 & 7)) * C_DIM + kc * 8;
    const __half* ap1 = g_vh +
        (((size_t)ti1 * H_DIM + wh1 * PS + (p0 >> 3)) * W_DIM + ww1 * PS + (p0 & 7)) * C_DIM + kc * 8;
    const uint32_t ao0 = (uint32_t)(r0 * STRB + kc * 16);
    const uint32_t ao1 = (uint32_t)((r0 + 64) * STRB + kc * 16);
    const __half* bp0 = g_wbt + (size_t)(n0 + r0) * 256 + kc * 8;
    const __half* bp1 = g_wbt + (size_t)(n0 + r0 + 64) * 256 + kc * 8;

    // ldmatrix per-thread offsets (bytes)
    const uint32_t a_off = (uint32_t)((wm * 64 + (lane & 7) + ((lane >> 3) & 1) * 8) * STRB
                                     + ((lane >> 4) & 1) * 16);
    const uint32_t b_off = (uint32_t)((wn * 32 + (lane & 7) + ((lane >> 4) & 1) * 8) * STRB
                                     + ((lane >> 3) & 1) * 16);

    float acc[4][4][4];
#pragma unroll
    for (int i = 0; i < 4; i++)
#pragma unroll
        for (int j = 0; j < 4; j++)
#pragma unroll
            for (int e = 0; e < 4; e++) acc[i][j][e] = 0.f;

    // Prologue: stages 0,1 (ktiles 0,1; ktile = 32 halves)
#pragma unroll
    for (int s = 0; s < 2; s++) {
        const int k0 = s * 32;
        cp16(su + s * TILE_STG + ao0, ap0 + k0);
        cp16(su + s * TILE_STG + ao1, ap1 + k0);
        cp16(su + B_BASE + s * TILE_STG + ao0, bp0 + k0);
        cp16(su + B_BASE + s * TILE_STG + ao1, bp1 + k0);
        CP_COMMIT();
    }

#pragma unroll 1
    for (int kt = 0; kt < 8; ++kt) {
        if (kt < 6) CP_WAIT(1); else CP_WAIT(0);
        __syncthreads();
        if (kt + 2 < 8) {
            const int s = (kt + 2) % NSTG;
            const int k0 = (kt + 2) * 32;
            cp16(su + s * TILE_STG + ao0, ap0 + k0);
            cp16(su + s * TILE_STG + ao1, ap1 + k0);
            cp16(su + B_BASE + s * TILE_STG + ao0, bp0 + k0);
            cp16(su + B_BASE + s * TILE_STG + ao1, bp1 + k0);
            CP_COMMIT();
        }

        const int buf = kt % NSTG;
        const uint32_t abase = su + buf * TILE_STG + a_off;
        const uint32_t bbase = su + B_BASE + buf * TILE_STG + b_off;
#pragma unroll
        for (int ks = 0; ks < 2; ks++) {           // 2 k16 steps per ktile
            uint32_t afr[4][4];
#pragma unroll
            for (int mf = 0; mf < 4; mf++)
                ldsm4(afr[mf][0], afr[mf][1], afr[mf][2], afr[mf][3],
                      abase + (uint32_t)(mf * 16 * STRB + ks * 32));
            uint32_t bfr[4][2];
            ldsm4(bfr[0][0], bfr[0][1], bfr[1][0], bfr[1][1],
                  bbase + (uint32_t)(ks * 32));
            ldsm4(bfr[2][0], bfr[2][1], bfr[3][0], bfr[3][1],
                  bbase + (uint32_t)(16 * STRB + ks * 32));
#pragma unroll
            for (int mf = 0; mf < 4; mf++)
#pragma unroll
                for (int nf = 0; nf < 4; nf++)
                    mma_f16(acc[mf][nf], afr[mf], bfr[nf]);
        }
    }

    // Epilogue: + modw (fp32), convert fp16, scatter to [n][h][p][d]
    const int seg = n0 >> 8;
    __half* dst = (seg == 0) ? g_q : (seg == 1) ? g_k : g_v;
#pragma unroll
    for (int mf = 0; mf < 4; mf++) {
        const int row0 = wm * 64 + mf * 16 + (lane >> 2);
#pragma unroll
        for (int nf = 0; nf < 4; nf++) {
            const int clg = n0 + wn * 32 + nf * 8 + (lane & 3) * 2;
            const int cc  = clg & 255;
            const int hh  = cc >> 5, d0 = cc & 31;
            const float* c4 = acc[mf][nf];
#pragma unroll
            for (int half_i = 0; half_i < 2; half_i++) {
                const int row = row0 + half_i * 8;
                const int win = n2 + (row >> 6);
                const int pp  = row & 63;
                const float2 mwv = *(const float2*)(g_mw + pp * 768 + clg);
                __half2 h2 = __floats2half2_rn(c4[half_i * 2 + 0] + mwv.x,
                                               c4[half_i * 2 + 1] + mwv.y);
                *(__half2*)(dst + (((size_t)win * NH + hh) * NTOK + pp) * HD + d0) = h2;
            }
        }
    }
}

// ---------------------------------------------------------------------------
// Kernel B (FP16 MMA attention): block = (window, head), 128 thr / 4 warps.
// ---------------------------------------------------------------------------
__global__ __launch_bounds__(128, 4) void attn_tc(const float* __restrict__ rpt)
{
    __shared__ __half Qs[64][40];     // stride 80B
    __shared__ __half Ks[64][40];
    __shared__ __half Vs[64][40];
    __shared__ float  Ps[64][68];     // S (fp32)
    __shared__ __half Ph[64][72];     // P (fp16), stride 144B (s16=9 odd)
    __shared__ float  bsb[226];

    const int b = blockIdx.x;
    const int h = b & 7;
    const int n = b >> 3;
    const int tid  = threadIdx.x;
    const int lane = tid & 31;
    const int warp = tid >> 5;
    const size_t base = (size_t)b * (NTOK * HD);

    // Stage Q/K/V (fp16, 16B chunks)
    {
        const uint32_t sq = (uint32_t)__cvta_generic_to_shared(Qs);
        const uint32_t sk = (uint32_t)__cvta_generic_to_shared(Ks);
        const uint32_t sv = (uint32_t)__cvta_generic_to_shared(Vs);
#pragma unroll
        for (int it = 0; it < 2; it++) {
            const int idx = tid + it * 128;   // 256 slots = 64 rows x 4 chunks
            const int p  = idx >> 2;
            const int q4 = idx & 3;
            cp16(sq + (uint32_t)(p * STRB + q4 * 16), g_q + base + p * 32 + q4 * 8);
            cp16(sk + (uint32_t)(p * STRB + q4 * 16), g_k + base + p * 32 + q4 * 8);
            cp16(sv + (uint32_t)(p * STRB + q4 * 16), g_v + base + p * 32 + q4 * 8);
        }
        CP_COMMIT();
        for (int i = tid; i < 225; i += 128) bsb[i] = rpt[(size_t)i * NH + h];
        CP_WAIT(0);
    }
    __syncthreads();

    const int t = lane & 3, g = lane >> 2;
    const uint32_t sqb = (uint32_t)__cvta_generic_to_shared(Qs);
    const uint32_t skb = (uint32_t)__cvta_generic_to_shared(Ks);
    const uint32_t svb = (uint32_t)__cvta_generic_to_shared(Vs);
    const uint32_t spb = (uint32_t)__cvta_generic_to_shared(Ph);

    const uint32_t arow = (lane & 7) + ((lane >> 3) & 1) * 8;   // A-quadrant row
    const uint32_t alk  = ((lane >> 4) & 1) * 16;               // A-quadrant k-chunk
    const uint32_t brow = (lane & 7) + ((lane >> 4) & 1) * 8;   // B-quadrant n-row
    const uint32_t blk  = ((lane >> 3) & 1) * 16;               // B-quadrant k-chunk

    // ---- QK^T: warp computes S[:, warp*16 .. +15] ----
    float acc[4][2][4];
#pragma unroll
    for (int i = 0; i < 4; i++)
#pragma unroll
        for (int j = 0; j < 2; j++)
#pragma unroll
            for (int e = 0; e < 4; e++) acc[i][j][e] = 0.f;

#pragma unroll
    for (int ks = 0; ks < 2; ks++) {             // d = 32 -> 2 k16 steps
        uint32_t af[4][4];
#pragma unroll
        for (int mt = 0; mt < 4; mt++)
            ldsm4(af[mt][0], af[mt][1], af[mt][2], af[mt][3],
                  sqb + (uint32_t)((mt * 16 + arow) * STRB + ks * 32) + alk);
        uint32_t bf[2][2];
        ldsm4(bf[0][0], bf[0][1], bf[1][0], bf[1][1],
              skb + (uint32_t)((warp * 16 + brow) * STRB + ks * 32) + blk);
#pragma unroll
        for (int mt = 0; mt < 4; mt++)
#pragma unroll
            for (int nt = 0; nt < 2; nt++)
                mma_f16(acc[mt][nt], af[mt], bf[nt]);
    }

    // S + rel-pos bias -> Ps (fp32)
#pragma unroll
    for (int mt = 0; mt < 4; mt++) {
#pragma unroll
        for (int nt = 0; nt < 2; nt++) {
            const int col = warp * 16 + nt * 8 + 2 * t;
            const int ky = col >> 3, kx = col & 7;
            const int ky1 = (col + 1) >> 3, kx1 = (col + 1) & 7;
            const float* c4 = acc[mt][nt];
#pragma unroll
            for (int half_i = 0; half_i < 2; half_i++) {
                const int r = mt * 16 + g + half_i * 8;
                const int qy = r >> 3, qx = r & 7;
                Ps[r][col]     = c4[half_i * 2 + 0] + bsb[(qy - ky  + 7) * 15 + (qx - kx  + 7)];
                Ps[r][col + 1] = c4[half_i * 2 + 1] + bsb[(qy - ky1 + 7) * 15 + (qx - kx1 + 7)];
            }
        }
    }
    __syncthreads();

    // ---- Softmax (fp32) -> Ph (fp16) ----
    {
        const int r  = tid >> 1;
        const int h0 = (tid & 1) * 32;
        float s[32];
        float mx = -1e30f;
#pragma unroll
        for (int j = 0; j < 32; j++) { s[j] = Ps[r][h0 + j]; mx = fmaxf(mx, s[j]); }
        mx = fmaxf(mx, __shfl_xor_sync(0xffffffffu, mx, 1));
        float sum = 0.f;
#pragma unroll
        for (int j = 0; j < 32; j++) { s[j] = __expf(s[j] - mx); sum += s[j]; }
        sum += __shfl_xor_sync(0xffffffffu, sum, 1);
        const float inv = 1.0f / sum;
        __half2* pr = (__half2*)&Ph[r][h0];
#pragma unroll
        for (int j = 0; j < 16; j++)
            pr[j] = __floats2half2_rn(s[2 * j] * inv, s[2 * j + 1] * inv);
    }
    __syncthreads();

    // ---- PV: warp computes O rows warp*16..+15, all 32 dims ----
    float acc2[4][4];
#pragma unroll
    for (int i = 0; i < 4; i++)
#pragma unroll
        for (int e = 0; e < 4; e++) acc2[i][e] = 0.f;

#pragma unroll
    for (int kt = 0; kt < 4; kt++) {             // tok = 64 -> 4 k16 steps
        uint32_t af[4];
        ldsm4(af[0], af[1], af[2], af[3],
              spb + (uint32_t)((warp * 16 + arow) * 144 + kt * 32) + alk);
        uint32_t bf[4][2];
        ldsm4t(bf[0][0], bf[0][1], bf[1][0], bf[1][1],
               svb + (uint32_t)((kt * 16 + arow) * STRB) + alk);
        ldsm4t(bf[2][0], bf[2][1], bf[3][0], bf[3][1],
               svb + (uint32_t)((kt * 16 + arow) * STRB + 32) + alk);
#pragma unroll
        for (int nt = 0; nt < 4; nt++)
            mma_f16(acc2[nt], af, bf[nt]);
    }

    // Write O (fp16) to g_o[n][p][h*32 + d]
#pragma unroll
    for (int nt = 0; nt < 4; nt++) {
        const int col = nt * 8 + 2 * t;
#pragma unroll
        for (int half_i = 0; half_i < 2; half_i++) {
            const int p = warp * 16 + g + half_i * 8;
            __half2 h2 = __floats2half2_rn(acc2[nt][half_i * 2 + 0],
                                           acc2[nt][half_i * 2 + 1]);
            *(__half2*)(g_o + ((size_t)n * NTOK + p) * C_DIM + h * HD + col) = h2;
        }
    }
}

// ---------------------------------------------------------------------------
// Kernel C (FP16 MMA + ldmatrix): proj GEMM + inverse window scatter.
// grid = (2, 2048).
// ---------------------------------------------------------------------------
__global__ __launch_bounds__(256, 2) void proj_tc(
    const float* __restrict__ pb, float* __restrict__ out)
{
    extern __shared__ uint32_t smem[];
    const uint32_t su = (uint32_t)__cvta_generic_to_shared(smem);

    const int tid  = threadIdx.x;
    const int lane = tid & 31;
    const int warp = tid >> 5;
    const int wm   = warp >> 2;
    const int wn   = warp & 3;
    const int rbase = blockIdx.y * 128;
    const int n0    = blockIdx.x * 128;

    const int r0 = tid >> 2;
    const int kc = tid & 3;
    const __half* ap0 = g_o + (size_t)(rbase + r0) * 256 + kc * 8;
    const __half* ap1 = g_o + (size_t)(rbase + r0 + 64) * 256 + kc * 8;
    const uint32_t ao0 = (uint32_t)(r0 * STRB + kc * 16);
    const uint32_t ao1 = (uint32_t)((r0 + 64) * STRB + kc * 16);
    const __half* bp0 = g_pwt + (size_t)(n0 + r0) * 256 + kc * 8;
    const __half* bp1 = g_pwt + (size_t)(n0 + r0 + 64) * 256 + kc * 8;

    const uint32_t a_off = (uint32_t)((wm * 64 + (lane & 7) + ((lane >> 3) & 1) * 8) * STRB
                                     + ((lane >> 4) & 1) * 16);
    const uint32_t b_off = (uint32_t)((wn * 32 + (lane & 7) + ((lane >> 4) & 1) * 8) * STRB
                                     + ((lane >> 3) & 1) * 16);

    float acc[4][4][4];
#pragma unroll
    for (int i = 0; i < 4; i++)
#pragma unroll
        for (int j = 0; j < 4; j++)
#pragma unroll
            for (int e = 0; e < 4; e++) acc[i][j][e] = 0.f;

#pragma unroll
    for (int s = 0; s < 2; s++) {
        const int k0 = s * 32;
        cp16(su + s * TILE_STG + ao0, ap0 + k0);
        cp16(su + s * TILE_STG + ao1, ap1 + k0);
        cp16(su + B_BASE + s * TILE_STG + ao0, bp0 + k0);
        cp16(su + B_BASE + s * TILE_STG + ao1, bp1 + k0);
        CP_COMMIT();
    }

#pragma unroll 1
    for (int kt = 0; kt < 8; ++kt) {
        if (kt < 6) CP_WAIT(1); else CP_WAIT(0);
        __syncthreads();
        if (kt + 2 < 8) {
            const int s = (kt + 2) % NSTG;
            const int k0 = (kt + 2) * 32;
            cp16(su + s * TILE_STG + ao0, ap0 + k0);
            cp16(su + s * TILE_STG + ao1, ap1 + k0);
            cp16(su + B_BASE + s * TILE_STG + ao0, bp0 + k0);
            cp16(su + B_BASE + s * TILE_STG + ao1, bp1 + k0);
            CP_COMMIT();
        }

        const int buf = kt % NSTG;
        const uint32_t abase = su + buf * TILE_STG + a_off;
        const uint32_t bbase = su + B_BASE + buf * TILE_STG + b_off;
#pragma unroll
        for (int ks = 0; ks < 2; ks++) {
            uint32_t afr[4][4];
#pragma unroll
            for (int mf = 0; mf < 4; mf++)
                ldsm4(afr[mf][0], afr[mf][1], afr[mf][2], afr[mf][3],
                      abase + (uint32_t)(mf * 16 * STRB + ks * 32));
            uint32_t bfr[4][2];
            ldsm4(bfr[0][0], bfr[0][1], bfr[1][0], bfr[1][1],
                  bbase + (uint32_t)(ks * 32));
            ldsm4(bfr[2][0], bfr[2][1], bfr[3][0], bfr[3][1],
                  bbase + (uint32_t)(16 * STRB + ks * 32));
#pragma unroll
            for (int mf = 0; mf < 4; mf++)
#pragma unroll
                for (int nf = 0; nf < 4; nf++)
                    mma_f16(acc[mf][nf], afr[mf], bfr[nf]);
        }
    }

    // Epilogue: + proj_b (fp32), inverse window scatter to (t,h,w,c)
#pragma unroll
    for (int mf = 0; mf < 4; mf++) {
        const int row0 = wm * 64 + mf * 16 + (lane >> 2);
#pragma unroll
        for (int nf = 0; nf < 4; nf++) {
            const int col = n0 + wn * 32 + nf * 8 + (lane & 3) * 2;
            const float b0 = pb[col], b1 = pb[col + 1];
            const float* c4 = acc[mf][nf];
#pragma unroll
            for (int half_i = 0; half_i < 2; half_i++) {
                const int grow = rbase + row0 + half_i * 8;
                const int win = grow >> 6;
                const int p   = grow & 63;
                const int t_idx = win >> 10, wh = (win >> 5) & 31, ww = win & 31;
                const int py = p >> 3, px = p & 7;
                const size_t pix =
                    (((size_t)t_idx * H_DIM + wh * PS + py) * W_DIM + ww * PS + px) * C_DIM;
                float2 v2;
                v2.x = c4[half_i * 2 + 0] + b0;
                v2.y = c4[half_i * 2 + 1] + b1;
                *(float2*)(out + pix + col) = v2;
            }
        }
    }
}

// ---------------------------------------------------------------------------
extern "C" void kernel_launch(void* const* d_in, const int* in_sizes, int n_in,
                              void* d_out, int out_size)
{
    const float* vid  = (const float*)d_in[0];
    const float* modu = (const float*)d_in[1];
    const float* wq   = (const float*)d_in[2];
    const float* bq   = (const float*)d_in[3];
    const float* wkv  = (const float*)d_in[4];
    const float* bkv  = (const float*)d_in[5];
    const float* pw   = (const float*)d_in[6];
    const float* pb   = (const float*)d_in[7];
    const float* rpt  = (const float*)d_in[8];
    float* out = (float*)d_out;

    cudaFuncSetAttribute(qkv_tc,  cudaFuncAttributeMaxDynamicSharedMemorySize, SMEM_DYN);
    cudaFuncSetAttribute(proj_tc, cudaFuncAttributeMaxDynamicSharedMemorySize, SMEM_DYN);

    prep_w<<<1024, 256>>>(wq, wkv, pw);
    prep_vid<<<65536, 256>>>(vid);
    prep_modw<<<64, 256>>>(modu, wq, bq, wkv, bkv);
    qkv_tc<<<dim3(6, 2048), 256, SMEM_DYN>>>();
    attn_tc<<<NWIN * NH, 128>>>(rpt);
    proj_tc<<<dim3(2, 2048), 256, SMEM_DYN>>>(pb, out);
}